// round 5
// baseline (speedup 1.0000x reference)
#include <cuda_runtime.h>
#include <cuda_bf16.h>
#include <cstdint>

// Problem constants
#define BB 4
#define SS 2048
#define DD 1024
#define HH 16
#define DKK 64
#define MROWS (BB*SS)          // 8192

// ---------------------------------------------------------------------------
// Scratch (device globals — no allocations allowed)
// ---------------------------------------------------------------------------
__device__ float g_q[BB*HH*SS*DKK];     // [B,H,S,DK] 32 MB
__device__ float g_k[BB*HH*SS*DKK];
__device__ float g_v[BB*HH*SS*DKK];
__device__ float g_att[BB*SS*DD];       // [B,S,D]    32 MB

// ---------------------------------------------------------------------------
// GEMM (NT):  C[i,j] = sum_k A[i,k] * W[j,k] + bias[j]
// A: [M,K] row-major, W: [N,K] row-major (PyTorch Linear weight layout)
// headsOut=1: write C in [B,H,S,DK] layout (for Q/K/V projections)
// headsOut=0: write C in [M,N] row-major  (for output projection)
// Tile: BM=128, BN=128, BK=16. 256 threads, 8x8 microtile per thread.
// M=8192, N=1024, K=1024 are exact multiples — no bounds checks.
// ---------------------------------------------------------------------------
__global__ __launch_bounds__(256) void gemm_nt_kernel(
    const float* __restrict__ A, const float* __restrict__ W,
    const float* __restrict__ bias, float* __restrict__ C,
    int M, int N, int K, int headsOut)
{
    __shared__ float As[16][132];   // [k][m], padded to soften store conflicts
    __shared__ float Ws[16][132];   // [k][n]

    const int tid = threadIdx.x;
    const int tx  = tid & 15;       // 0..15 -> n microtile
    const int ty  = tid >> 4;       // 0..15 -> m microtile
    const int mBase = blockIdx.y * 128;
    const int nBase = blockIdx.x * 128;

    float acc[8][8];
#pragma unroll
    for (int i = 0; i < 8; i++)
#pragma unroll
        for (int j = 0; j < 8; j++) acc[i][j] = 0.f;

    for (int k0 = 0; k0 < K; k0 += 16) {
        // Load 128x16 A tile and 128x16 W tile: 512 float4 each, 2 per thread.
#pragma unroll
        for (int li = 0; li < 2; li++) {
            int f   = tid + li * 256;
            int row = f >> 2;              // 0..127
            int kc  = (f & 3) << 2;        // 0,4,8,12
            float4 a = *reinterpret_cast<const float4*>(
                A + (size_t)(mBase + row) * K + k0 + kc);
            As[kc + 0][row] = a.x; As[kc + 1][row] = a.y;
            As[kc + 2][row] = a.z; As[kc + 3][row] = a.w;
            float4 w = *reinterpret_cast<const float4*>(
                W + (size_t)(nBase + row) * K + k0 + kc);
            Ws[kc + 0][row] = w.x; Ws[kc + 1][row] = w.y;
            Ws[kc + 2][row] = w.z; Ws[kc + 3][row] = w.w;
        }
        __syncthreads();

#pragma unroll
        for (int kk = 0; kk < 16; kk++) {
            float af[8], bf[8];
            *reinterpret_cast<float4*>(af)     = *reinterpret_cast<const float4*>(&As[kk][ty * 8]);
            *reinterpret_cast<float4*>(af + 4) = *reinterpret_cast<const float4*>(&As[kk][ty * 8 + 4]);
            *reinterpret_cast<float4*>(bf)     = *reinterpret_cast<const float4*>(&Ws[kk][tx * 8]);
            *reinterpret_cast<float4*>(bf + 4) = *reinterpret_cast<const float4*>(&Ws[kk][tx * 8 + 4]);
#pragma unroll
            for (int i = 0; i < 8; i++)
#pragma unroll
                for (int j = 0; j < 8; j++)
                    acc[i][j] = fmaf(af[i], bf[j], acc[i][j]);
        }
        __syncthreads();
    }

    // Epilogue
    float bv[8];
#pragma unroll
    for (int j = 0; j < 8; j++) bv[j] = bias[nBase + tx * 8 + j];

    if (!headsOut) {
#pragma unroll
        for (int i = 0; i < 8; i++) {
            size_t rowOff = (size_t)(mBase + ty * 8 + i) * N + nBase + tx * 8;
#pragma unroll
            for (int j = 0; j < 8; j++)
                C[rowOff + j] = acc[i][j] + bv[j];
        }
    } else {
        // C logical [M=B*S, N=H*DK] -> physical [B,H,S,DK]
#pragma unroll
        for (int i = 0; i < 8; i++) {
            int gi = mBase + ty * 8 + i;
            int b  = gi >> 11;             // /2048
            int s  = gi & 2047;
#pragma unroll
            for (int j = 0; j < 8; j++) {
                int gj = nBase + tx * 8 + j;
                int h  = gj >> 6;
                int dk = gj & 63;
                C[(size_t)((b * HH + h) * SS + s) * DKK + dk] = acc[i][j] + bv[j];
            }
        }
    }
}

// ---------------------------------------------------------------------------
// Flash attention: one thread owns one query row.
// Q,K,V in [B,H,S,DK]. Output written in [B,S,D] layout for the final GEMM.
// BQ = 128 rows per CTA (1 per thread), key tiles of BK = 16.
// ---------------------------------------------------------------------------
__global__ __launch_bounds__(128) void attn_kernel(
    const float* __restrict__ Q, const float* __restrict__ K,
    const float* __restrict__ V, float* __restrict__ O)
{
    __shared__ float4 Ks[16][16];   // [BK][DK/4]
    __shared__ float4 Vs[16][16];

    const int bh   = blockIdx.y;                       // 0..63  (b*H+h)
    const int qrow = blockIdx.x * 128 + threadIdx.x;   // 0..2047

    const float*  Qb  = Q + (size_t)bh * SS * DKK;
    const float4* Kb4 = reinterpret_cast<const float4*>(K + (size_t)bh * SS * DKK);
    const float4* Vb4 = reinterpret_cast<const float4*>(V + (size_t)bh * SS * DKK);

    // q row in registers, pre-scaled by 1/sqrt(DK) = 0.125
    float4 q[16];
    const float4* qp = reinterpret_cast<const float4*>(Qb + (size_t)qrow * DKK);
#pragma unroll
    for (int i = 0; i < 16; i++) {
        float4 t = qp[i];
        t.x *= 0.125f; t.y *= 0.125f; t.z *= 0.125f; t.w *= 0.125f;
        q[i] = t;
    }

    float4 o[16];
#pragma unroll
    for (int i = 0; i < 16; i++) o[i] = make_float4(0.f, 0.f, 0.f, 0.f);
    float m = -1e30f, l = 0.f;

    for (int t = 0; t < SS / 16; t++) {
        __syncthreads();
        // Stage K,V tile: 16x64 floats = 256 float4 each; 2 per thread.
        int base = t * 256;
        reinterpret_cast<float4*>(Ks)[threadIdx.x]       = Kb4[base + threadIdx.x];
        reinterpret_cast<float4*>(Ks)[threadIdx.x + 128] = Kb4[base + threadIdx.x + 128];
        reinterpret_cast<float4*>(Vs)[threadIdx.x]       = Vb4[base + threadIdx.x];
        reinterpret_cast<float4*>(Vs)[threadIdx.x + 128] = Vb4[base + threadIdx.x + 128];
        __syncthreads();

        // scores for this tile (already scaled via q)
        float s[16];
#pragma unroll
        for (int j = 0; j < 16; j++) {
            float a0 = 0.f, a1 = 0.f, a2 = 0.f, a3 = 0.f;
#pragma unroll
            for (int d = 0; d < 16; d += 4) {
                float4 k0 = Ks[j][d + 0];
                a0 = fmaf(q[d + 0].x, k0.x, a0); a0 = fmaf(q[d + 0].y, k0.y, a0);
                a0 = fmaf(q[d + 0].z, k0.z, a0); a0 = fmaf(q[d + 0].w, k0.w, a0);
                float4 k1 = Ks[j][d + 1];
                a1 = fmaf(q[d + 1].x, k1.x, a1); a1 = fmaf(q[d + 1].y, k1.y, a1);
                a1 = fmaf(q[d + 1].z, k1.z, a1); a1 = fmaf(q[d + 1].w, k1.w, a1);
                float4 k2 = Ks[j][d + 2];
                a2 = fmaf(q[d + 2].x, k2.x, a2); a2 = fmaf(q[d + 2].y, k2.y, a2);
                a2 = fmaf(q[d + 2].z, k2.z, a2); a2 = fmaf(q[d + 2].w, k2.w, a2);
                float4 k3 = Ks[j][d + 3];
                a3 = fmaf(q[d + 3].x, k3.x, a3); a3 = fmaf(q[d + 3].y, k3.y, a3);
                a3 = fmaf(q[d + 3].z, k3.z, a3); a3 = fmaf(q[d + 3].w, k3.w, a3);
            }
            s[j] = (a0 + a1) + (a2 + a3);
        }

        // online softmax update
        float tmax = s[0];
#pragma unroll
        for (int j = 1; j < 16; j++) tmax = fmaxf(tmax, s[j]);
        float mn   = fmaxf(m, tmax);
        float corr = __expf(m - mn);
        m = mn;
        l *= corr;
#pragma unroll
        for (int i = 0; i < 16; i++) {
            o[i].x *= corr; o[i].y *= corr; o[i].z *= corr; o[i].w *= corr;
        }

#pragma unroll
        for (int j = 0; j < 16; j++) {
            float p = __expf(s[j] - mn);
            l += p;
#pragma unroll
            for (int d = 0; d < 16; d++) {
                float4 v = Vs[j][d];
                o[d].x = fmaf(p, v.x, o[d].x);
                o[d].y = fmaf(p, v.y, o[d].y);
                o[d].z = fmaf(p, v.z, o[d].z);
                o[d].w = fmaf(p, v.w, o[d].w);
            }
        }
    }

    // normalize and write to [B,S,D]
    float inv = 1.f / l;
    int b = bh >> 4, h = bh & 15;
    float4* op = reinterpret_cast<float4*>(
        O + ((size_t)(b * SS + qrow) * DD + h * DKK));
#pragma unroll
    for (int i = 0; i < 16; i++) {
        float4 t = o[i];
        t.x *= inv; t.y *= inv; t.z *= inv; t.w *= inv;
        op[i] = t;
    }
}

// ---------------------------------------------------------------------------
// kernel_launch
// ---------------------------------------------------------------------------
extern "C" void kernel_launch(void* const* d_in, const int* in_sizes, int n_in,
                              void* d_out, int out_size)
{
    const float* query = (const float*)d_in[0];
    const float* key   = (const float*)d_in[1];
    const float* value = (const float*)d_in[2];
    const float* Wq    = (const float*)d_in[3];
    const float* bq    = (const float*)d_in[4];
    const float* Wk    = (const float*)d_in[5];
    const float* bk    = (const float*)d_in[6];
    const float* Wv    = (const float*)d_in[7];
    const float* bv    = (const float*)d_in[8];
    const float* Wo    = (const float*)d_in[9];
    const float* bo    = (const float*)d_in[10];
    float* out = (float*)d_out;

    float *qp, *kp, *vp, *ap;
    cudaGetSymbolAddress((void**)&qp, g_q);
    cudaGetSymbolAddress((void**)&kp, g_k);
    cudaGetSymbolAddress((void**)&vp, g_v);
    cudaGetSymbolAddress((void**)&ap, g_att);

    dim3 gGrid(DD / 128, MROWS / 128);   // (8, 64)
    dim3 gBlk(256);

    // Projections -> [B,H,S,DK]
    gemm_nt_kernel<<<gGrid, gBlk>>>(query, Wq, bq, qp, MROWS, DD, DD, 1);
    gemm_nt_kernel<<<gGrid, gBlk>>>(key,   Wk, bk, kp, MROWS, DD, DD, 1);
    gemm_nt_kernel<<<gGrid, gBlk>>>(value, Wv, bv, vp, MROWS, DD, DD, 1);

    // Attention -> [B,S,D]
    dim3 aGrid(SS / 128, BB * HH);       // (16, 64)
    attn_kernel<<<aGrid, 128>>>(qp, kp, vp, ap);

    // Output projection -> d_out [B,S,D]
    gemm_nt_kernel<<<gGrid, gBlk>>>(ap, Wo, bo, out, MROWS, DD, DD, 0);
}

// round 6
// speedup vs baseline: 1.0002x; 1.0002x over previous
#include <cuda_runtime.h>
#include <cuda_bf16.h>
#include <cstdint>

// Problem constants
#define BB 4
#define SS 2048
#define DD 1024
#define HH 16
#define DKK 64
#define MROWS (BB*SS)          // 8192

// ---------------------------------------------------------------------------
// Scratch (device globals — no allocations allowed)
// ---------------------------------------------------------------------------
__device__ float g_q[BB*HH*SS*DKK];     // [B,H,S,DK] 32 MB
__device__ float g_k[BB*HH*SS*DKK];
__device__ float g_v[BB*HH*SS*DKK];
__device__ float g_att[BB*SS*DD];       // [B,S,D]    32 MB

// ---------------------------------------------------------------------------
// GEMM (NT):  C[i,j] = sum_k A[i,k] * W[j,k] + bias[j]
// A: [M,K] row-major, W: [N,K] row-major (PyTorch Linear weight layout)
// headsOut=1: write C in [B,H,S,DK] layout (for Q/K/V projections)
// headsOut=0: write C in [M,N] row-major  (for output projection)
// Tile: BM=128, BN=128, BK=16. 256 threads, 8x8 microtile per thread.
// M=8192, N=1024, K=1024 are exact multiples — no bounds checks.
// ---------------------------------------------------------------------------
__global__ __launch_bounds__(256) void gemm_nt_kernel(
    const float* __restrict__ A, const float* __restrict__ W,
    const float* __restrict__ bias, float* __restrict__ C,
    int M, int N, int K, int headsOut)
{
    __shared__ float As[16][132];   // [k][m], padded to soften store conflicts
    __shared__ float Ws[16][132];   // [k][n]

    const int tid = threadIdx.x;
    const int tx  = tid & 15;       // 0..15 -> n microtile
    const int ty  = tid >> 4;       // 0..15 -> m microtile
    const int mBase = blockIdx.y * 128;
    const int nBase = blockIdx.x * 128;

    float acc[8][8];
#pragma unroll
    for (int i = 0; i < 8; i++)
#pragma unroll
        for (int j = 0; j < 8; j++) acc[i][j] = 0.f;

    for (int k0 = 0; k0 < K; k0 += 16) {
        // Load 128x16 A tile and 128x16 W tile: 512 float4 each, 2 per thread.
#pragma unroll
        for (int li = 0; li < 2; li++) {
            int f   = tid + li * 256;
            int row = f >> 2;              // 0..127
            int kc  = (f & 3) << 2;        // 0,4,8,12
            float4 a = *reinterpret_cast<const float4*>(
                A + (size_t)(mBase + row) * K + k0 + kc);
            As[kc + 0][row] = a.x; As[kc + 1][row] = a.y;
            As[kc + 2][row] = a.z; As[kc + 3][row] = a.w;
            float4 w = *reinterpret_cast<const float4*>(
                W + (size_t)(nBase + row) * K + k0 + kc);
            Ws[kc + 0][row] = w.x; Ws[kc + 1][row] = w.y;
            Ws[kc + 2][row] = w.z; Ws[kc + 3][row] = w.w;
        }
        __syncthreads();

#pragma unroll
        for (int kk = 0; kk < 16; kk++) {
            float af[8], bf[8];
            *reinterpret_cast<float4*>(af)     = *reinterpret_cast<const float4*>(&As[kk][ty * 8]);
            *reinterpret_cast<float4*>(af + 4) = *reinterpret_cast<const float4*>(&As[kk][ty * 8 + 4]);
            *reinterpret_cast<float4*>(bf)     = *reinterpret_cast<const float4*>(&Ws[kk][tx * 8]);
            *reinterpret_cast<float4*>(bf + 4) = *reinterpret_cast<const float4*>(&Ws[kk][tx * 8 + 4]);
#pragma unroll
            for (int i = 0; i < 8; i++)
#pragma unroll
                for (int j = 0; j < 8; j++)
                    acc[i][j] = fmaf(af[i], bf[j], acc[i][j]);
        }
        __syncthreads();
    }

    // Epilogue
    float bv[8];
#pragma unroll
    for (int j = 0; j < 8; j++) bv[j] = bias[nBase + tx * 8 + j];

    if (!headsOut) {
#pragma unroll
        for (int i = 0; i < 8; i++) {
            size_t rowOff = (size_t)(mBase + ty * 8 + i) * N + nBase + tx * 8;
#pragma unroll
            for (int j = 0; j < 8; j++)
                C[rowOff + j] = acc[i][j] + bv[j];
        }
    } else {
        // C logical [M=B*S, N=H*DK] -> physical [B,H,S,DK]
#pragma unroll
        for (int i = 0; i < 8; i++) {
            int gi = mBase + ty * 8 + i;
            int b  = gi >> 11;             // /2048
            int s  = gi & 2047;
#pragma unroll
            for (int j = 0; j < 8; j++) {
                int gj = nBase + tx * 8 + j;
                int h  = gj >> 6;
                int dk = gj & 63;
                C[(size_t)((b * HH + h) * SS + s) * DKK + dk] = acc[i][j] + bv[j];
            }
        }
    }
}

// ---------------------------------------------------------------------------
// Flash attention: one thread owns one query row.
// Q,K,V in [B,H,S,DK]. Output written in [B,S,D] layout for the final GEMM.
// BQ = 128 rows per CTA (1 per thread), key tiles of BK = 16.
// ---------------------------------------------------------------------------
__global__ __launch_bounds__(128) void attn_kernel(
    const float* __restrict__ Q, const float* __restrict__ K,
    const float* __restrict__ V, float* __restrict__ O)
{
    __shared__ float4 Ks[16][16];   // [BK][DK/4]
    __shared__ float4 Vs[16][16];

    const int bh   = blockIdx.y;                       // 0..63  (b*H+h)
    const int qrow = blockIdx.x * 128 + threadIdx.x;   // 0..2047

    const float*  Qb  = Q + (size_t)bh * SS * DKK;
    const float4* Kb4 = reinterpret_cast<const float4*>(K + (size_t)bh * SS * DKK);
    const float4* Vb4 = reinterpret_cast<const float4*>(V + (size_t)bh * SS * DKK);

    // q row in registers, pre-scaled by 1/sqrt(DK) = 0.125
    float4 q[16];
    const float4* qp = reinterpret_cast<const float4*>(Qb + (size_t)qrow * DKK);
#pragma unroll
    for (int i = 0; i < 16; i++) {
        float4 t = qp[i];
        t.x *= 0.125f; t.y *= 0.125f; t.z *= 0.125f; t.w *= 0.125f;
        q[i] = t;
    }

    float4 o[16];
#pragma unroll
    for (int i = 0; i < 16; i++) o[i] = make_float4(0.f, 0.f, 0.f, 0.f);
    float m = -1e30f, l = 0.f;

    for (int t = 0; t < SS / 16; t++) {
        __syncthreads();
        // Stage K,V tile: 16x64 floats = 256 float4 each; 2 per thread.
        int base = t * 256;
        reinterpret_cast<float4*>(Ks)[threadIdx.x]       = Kb4[base + threadIdx.x];
        reinterpret_cast<float4*>(Ks)[threadIdx.x + 128] = Kb4[base + threadIdx.x + 128];
        reinterpret_cast<float4*>(Vs)[threadIdx.x]       = Vb4[base + threadIdx.x];
        reinterpret_cast<float4*>(Vs)[threadIdx.x + 128] = Vb4[base + threadIdx.x + 128];
        __syncthreads();

        // scores for this tile (already scaled via q)
        float s[16];
#pragma unroll
        for (int j = 0; j < 16; j++) {
            float a0 = 0.f, a1 = 0.f, a2 = 0.f, a3 = 0.f;
#pragma unroll
            for (int d = 0; d < 16; d += 4) {
                float4 k0 = Ks[j][d + 0];
                a0 = fmaf(q[d + 0].x, k0.x, a0); a0 = fmaf(q[d + 0].y, k0.y, a0);
                a0 = fmaf(q[d + 0].z, k0.z, a0); a0 = fmaf(q[d + 0].w, k0.w, a0);
                float4 k1 = Ks[j][d + 1];
                a1 = fmaf(q[d + 1].x, k1.x, a1); a1 = fmaf(q[d + 1].y, k1.y, a1);
                a1 = fmaf(q[d + 1].z, k1.z, a1); a1 = fmaf(q[d + 1].w, k1.w, a1);
                float4 k2 = Ks[j][d + 2];
                a2 = fmaf(q[d + 2].x, k2.x, a2); a2 = fmaf(q[d + 2].y, k2.y, a2);
                a2 = fmaf(q[d + 2].z, k2.z, a2); a2 = fmaf(q[d + 2].w, k2.w, a2);
                float4 k3 = Ks[j][d + 3];
                a3 = fmaf(q[d + 3].x, k3.x, a3); a3 = fmaf(q[d + 3].y, k3.y, a3);
                a3 = fmaf(q[d + 3].z, k3.z, a3); a3 = fmaf(q[d + 3].w, k3.w, a3);
            }
            s[j] = (a0 + a1) + (a2 + a3);
        }

        // online softmax update
        float tmax = s[0];
#pragma unroll
        for (int j = 1; j < 16; j++) tmax = fmaxf(tmax, s[j]);
        float mn   = fmaxf(m, tmax);
        float corr = __expf(m - mn);
        m = mn;
        l *= corr;
#pragma unroll
        for (int i = 0; i < 16; i++) {
            o[i].x *= corr; o[i].y *= corr; o[i].z *= corr; o[i].w *= corr;
        }

#pragma unroll
        for (int j = 0; j < 16; j++) {
            float p = __expf(s[j] - mn);
            l += p;
#pragma unroll
            for (int d = 0; d < 16; d++) {
                float4 v = Vs[j][d];
                o[d].x = fmaf(p, v.x, o[d].x);
                o[d].y = fmaf(p, v.y, o[d].y);
                o[d].z = fmaf(p, v.z, o[d].z);
                o[d].w = fmaf(p, v.w, o[d].w);
            }
        }
    }

    // normalize and write to [B,S,D]
    float inv = 1.f / l;
    int b = bh >> 4, h = bh & 15;
    float4* op = reinterpret_cast<float4*>(
        O + ((size_t)(b * SS + qrow) * DD + h * DKK));
#pragma unroll
    for (int i = 0; i < 16; i++) {
        float4 t = o[i];
        t.x *= inv; t.y *= inv; t.z *= inv; t.w *= inv;
        op[i] = t;
    }
}

// ---------------------------------------------------------------------------
// kernel_launch
// ---------------------------------------------------------------------------
extern "C" void kernel_launch(void* const* d_in, const int* in_sizes, int n_in,
                              void* d_out, int out_size)
{
    const float* query = (const float*)d_in[0];
    const float* key   = (const float*)d_in[1];
    const float* value = (const float*)d_in[2];
    const float* Wq    = (const float*)d_in[3];
    const float* bq    = (const float*)d_in[4];
    const float* Wk    = (const float*)d_in[5];
    const float* bk    = (const float*)d_in[6];
    const float* Wv    = (const float*)d_in[7];
    const float* bv    = (const float*)d_in[8];
    const float* Wo    = (const float*)d_in[9];
    const float* bo    = (const float*)d_in[10];
    float* out = (float*)d_out;

    float *qp, *kp, *vp, *ap;
    cudaGetSymbolAddress((void**)&qp, g_q);
    cudaGetSymbolAddress((void**)&kp, g_k);
    cudaGetSymbolAddress((void**)&vp, g_v);
    cudaGetSymbolAddress((void**)&ap, g_att);

    dim3 gGrid(DD / 128, MROWS / 128);   // (8, 64)
    dim3 gBlk(256);

    // Projections -> [B,H,S,DK]
    gemm_nt_kernel<<<gGrid, gBlk>>>(query, Wq, bq, qp, MROWS, DD, DD, 1);
    gemm_nt_kernel<<<gGrid, gBlk>>>(key,   Wk, bk, kp, MROWS, DD, DD, 1);
    gemm_nt_kernel<<<gGrid, gBlk>>>(value, Wv, bv, vp, MROWS, DD, DD, 1);

    // Attention -> [B,S,D]
    dim3 aGrid(SS / 128, BB * HH);       // (16, 64)
    attn_kernel<<<aGrid, 128>>>(qp, kp, vp, ap);

    // Output projection -> d_out [B,S,D]
    gemm_nt_kernel<<<gGrid, gBlk>>>(ap, Wo, bo, out, MROWS, DD, DD, 0);
}

// round 8
// speedup vs baseline: 1.0479x; 1.0477x over previous
#include <cuda_runtime.h>
#include <cuda_bf16.h>
#include <cstdint>

// Problem constants
#define BB 4
#define SS 2048
#define DD 1024
#define HH 16
#define DKK 64
#define MROWS (BB*SS)          // 8192

// ---------------------------------------------------------------------------
// Scratch (device globals — no allocations allowed)
// ---------------------------------------------------------------------------
__device__ float g_q[MROWS*DD];            // [B,S,D] fp32
__device__ float g_k[MROWS*DD];
__device__ float g_v[MROWS*DD];
__device__ float g_att[MROWS*DD];
__device__ __nv_bfloat16 g_ah[MROWS*DD];   // activation split hi/lo (reused per GEMM)
__device__ __nv_bfloat16 g_al[MROWS*DD];
__device__ __nv_bfloat16 g_wh[DD*DD];      // weight split hi/lo (reused per GEMM)
__device__ __nv_bfloat16 g_wl[DD*DD];

// ---------------------------------------------------------------------------
// Helpers
// ---------------------------------------------------------------------------
__device__ __forceinline__ uint32_t smem_u32(const void* p) {
    uint32_t a;
    asm("{ .reg .u64 t; cvta.to.shared.u64 t, %1; cvt.u32.u64 %0, t; }" : "=r"(a) : "l"(p));
    return a;
}
#define SWZ128(o) ((o) ^ (((o) >> 3) & 0x70))

#define CP_ASYNC16(dst, src) \
    asm volatile("cp.async.cg.shared.global [%0], [%1], 16;" :: "r"(dst), "l"(src))
#define CP_COMMIT()  asm volatile("cp.async.commit_group;" ::: "memory")
#define CP_WAIT0()   asm volatile("cp.async.wait_group 0;" ::: "memory")

__device__ __forceinline__ void ldsm_x4(uint32_t* r, uint32_t addr) {
    asm volatile("ldmatrix.sync.aligned.m8n8.x4.shared.b16 {%0,%1,%2,%3}, [%4];"
        : "=r"(r[0]), "=r"(r[1]), "=r"(r[2]), "=r"(r[3]) : "r"(addr));
}
__device__ __forceinline__ void ldsm_x2(uint32_t* r, uint32_t addr) {
    asm volatile("ldmatrix.sync.aligned.m8n8.x2.shared.b16 {%0,%1}, [%2];"
        : "=r"(r[0]), "=r"(r[1]) : "r"(addr));
}
__device__ __forceinline__ void mma16816(float* d, const uint32_t* a, const uint32_t* b) {
    asm volatile("mma.sync.aligned.m16n8k16.row.col.f32.bf16.bf16.f32 "
        "{%0,%1,%2,%3}, {%4,%5,%6,%7}, {%8,%9}, {%0,%1,%2,%3};"
        : "+f"(d[0]), "+f"(d[1]), "+f"(d[2]), "+f"(d[3])
        : "r"(a[0]), "r"(a[1]), "r"(a[2]), "r"(a[3]), "r"(b[0]), "r"(b[1]));
}

// packed f32x2 ops (sm_100-family base ISA, non-'a')
__device__ __forceinline__ unsigned long long pack2(float x, float y) {
    unsigned long long r; asm("mov.b64 %0, {%1, %2};" : "=l"(r) : "f"(x), "f"(y)); return r;
}
__device__ __forceinline__ float2 unpack2(unsigned long long v) {
    float2 f; asm("mov.b64 {%0, %1}, %2;" : "=f"(f.x), "=f"(f.y) : "l"(v)); return f;
}
#define FMA2(d, a, b) asm("fma.rn.f32x2 %0, %1, %2, %3;" : "=l"(d) : "l"(a), "l"(b), "l"(d))
#define MUL2(d, a, b) asm("mul.rn.f32x2 %0, %1, %2;"     : "=l"(d) : "l"(a), "l"(b))

// ---------------------------------------------------------------------------
// Split fp32 -> (bf16 hi, bf16 lo) with residual capture
// ---------------------------------------------------------------------------
__global__ __launch_bounds__(256) void split_kernel(
    const float* __restrict__ x, __nv_bfloat16* __restrict__ hi,
    __nv_bfloat16* __restrict__ lo, int n4)
{
    int i = blockIdx.x * 256 + threadIdx.x;
    if (i >= n4) return;
    float4 v = reinterpret_cast<const float4*>(x)[i];
    __nv_bfloat162 h0 = __floats2bfloat162_rn(v.x, v.y);
    __nv_bfloat162 h1 = __floats2bfloat162_rn(v.z, v.w);
    float r0 = v.x - __low2float(h0), r1 = v.y - __high2float(h0);
    float r2 = v.z - __low2float(h1), r3 = v.w - __high2float(h1);
    __nv_bfloat162* hp = reinterpret_cast<__nv_bfloat162*>(hi);
    __nv_bfloat162* lp = reinterpret_cast<__nv_bfloat162*>(lo);
    hp[2*i]   = h0;
    hp[2*i+1] = h1;
    lp[2*i]   = __floats2bfloat162_rn(r0, r1);
    lp[2*i+1] = __floats2bfloat162_rn(r2, r3);
}

// ---------------------------------------------------------------------------
// HMMA bf16x3 GEMM (NT): C[i,j] = sum_k A[i,k]*W[j,k] + bias[j]
// A=(Ah,Al) [M,K] bf16, W=(Bh,Bl) [N,K] bf16, fp32 register accumulators.
// CTA tile 128x128, K chunk 64 (SW128-swizzled 128B rows), cp.async
// double-buffered. 8 warps in 2(m) x 4(n); warp tile 64x32 via m16n8k16.
// ---------------------------------------------------------------------------
#define TILE_BYTES 16384               // 128 rows x 128B
#define BUF_BYTES  (4*TILE_BYTES)      // Ah,Al,Bh,Bl
#define GEMM_SMEM  (1024 + 2*BUF_BYTES)

__global__ __launch_bounds__(256, 1) void gemm_tc_kernel(
    const __nv_bfloat16* __restrict__ Ah, const __nv_bfloat16* __restrict__ Al,
    const __nv_bfloat16* __restrict__ Bh, const __nv_bfloat16* __restrict__ Bl,
    const float* __restrict__ bias, float* __restrict__ C)
{
    extern __shared__ char smem[];
    const uint32_t sbase = (smem_u32(smem) + 1023u) & ~1023u;
    const int tid = threadIdx.x;
    const int wid = tid >> 5;
    const int lid = tid & 31;
    const int wm  = wid >> 2;          // 0..1
    const int wn  = wid & 3;           // 0..3
    const int nBase = blockIdx.x * 128;
    const int mBase = blockIdx.y * 128;

    // Source bases in uint4 units (row stride = 1024 bf16 = 128 uint4)
    const uint4* srcs[4] = {
        reinterpret_cast<const uint4*>(Ah) + (size_t)mBase * 128,
        reinterpret_cast<const uint4*>(Al) + (size_t)mBase * 128,
        reinterpret_cast<const uint4*>(Bh) + (size_t)nBase * 128,
        reinterpret_cast<const uint4*>(Bl) + (size_t)nBase * 128
    };

    // Issue cp.async for one K-chunk (64 bf16) into buffer `buf`
    auto load_chunk = [&](int ch, int buf) {
        const int kq = ch * 8;         // k offset in uint4 units
        const uint32_t bufAddr = sbase + buf * BUF_BYTES;
#pragma unroll
        for (int t = 0; t < 16; t++) {
            const int tile = t >> 2;
            const int i = tid + (t & 3) * 256;   // 0..1023
            const int r = i >> 3, c = i & 7;
            const uint4* src = srcs[tile] + (size_t)r * 128 + kq + c;
            uint32_t dst = bufAddr + tile * TILE_BYTES + SWZ128(r * 128 + c * 16);
            CP_ASYNC16(dst, src);
        }
        CP_COMMIT();
    };

    float acc[4][4][4];
#pragma unroll
    for (int mt = 0; mt < 4; mt++)
#pragma unroll
        for (int nt = 0; nt < 4; nt++)
#pragma unroll
            for (int r = 0; r < 4; r++) acc[mt][nt][r] = 0.f;

    load_chunk(0, 0);
    CP_WAIT0();
    __syncthreads();

    // fragment address components (per-thread, chunk-invariant)
    const int aRow = wm * 64 + (lid & 15);
    const int aColH = (lid >> 4) * 16;           // 0 or 16 bytes
    const int bRow = wn * 32 + (lid & 7);
    const int bColH = ((lid >> 3) & 1) * 16;

#pragma unroll 1
    for (int ch = 0; ch < 16; ch++) {
        const int cur = ch & 1;
        if (ch < 15) load_chunk(ch + 1, cur ^ 1);

        const uint32_t bufAddr = sbase + cur * BUF_BYTES;
        const uint32_t aH = bufAddr;
        const uint32_t aL = bufAddr + TILE_BYTES;
        const uint32_t bH = bufAddr + 2 * TILE_BYTES;
        const uint32_t bL = bufAddr + 3 * TILE_BYTES;

#pragma unroll
        for (int ks = 0; ks < 4; ks++) {
            const int kByte = ks * 32;
            uint32_t ah[4][4], al[4][4], bh[4][2], bl[4][2];
#pragma unroll
            for (int mt = 0; mt < 4; mt++) {
                uint32_t off = SWZ128((aRow + mt * 16) * 128 + kByte + aColH);
                ldsm_x4(ah[mt], aH + off);
                ldsm_x4(al[mt], aL + off);
            }
#pragma unroll
            for (int nt = 0; nt < 4; nt++) {
                uint32_t off = SWZ128((bRow + nt * 8) * 128 + kByte + bColH);
                ldsm_x2(bh[nt], bH + off);
                ldsm_x2(bl[nt], bL + off);
            }
#pragma unroll
            for (int mt = 0; mt < 4; mt++)
#pragma unroll
                for (int nt = 0; nt < 4; nt++) {
                    mma16816(acc[mt][nt], ah[mt], bh[nt]);
                    mma16816(acc[mt][nt], ah[mt], bl[nt]);
                    mma16816(acc[mt][nt], al[mt], bh[nt]);
                }
        }

        if (ch < 15) CP_WAIT0();
        __syncthreads();
    }

    // Epilogue: direct global write with bias
    const int erow = mBase + wm * 64 + (lid >> 2);
    const int ecolBase = nBase + wn * 32 + 2 * (lid & 3);
#pragma unroll
    for (int nt = 0; nt < 4; nt++) {
        const int col = ecolBase + nt * 8;
        const float b0 = __ldg(bias + col), b1 = __ldg(bias + col + 1);
#pragma unroll
        for (int mt = 0; mt < 4; mt++) {
            const int r0 = erow + mt * 16;
            float2 v0 = make_float2(acc[mt][nt][0] + b0, acc[mt][nt][1] + b1);
            float2 v1 = make_float2(acc[mt][nt][2] + b0, acc[mt][nt][3] + b1);
            *reinterpret_cast<float2*>(C + (size_t)r0 * DD + col)       = v0;
            *reinterpret_cast<float2*>(C + (size_t)(r0 + 8) * DD + col) = v1;
        }
    }
}

// ---------------------------------------------------------------------------
// Flash attention with packed f32x2 FMA. Q,K,V,O all [B,S,D] fp32; head h
// occupies column block h*64..h*64+63. Two threads per query row (32 dims
// each), shfl_xor(1) combines score partials. Register-prefetched K/V tiles.
// ---------------------------------------------------------------------------
__global__ __launch_bounds__(256, 2) void attn_kernel(
    const float* __restrict__ Q, const float* __restrict__ K,
    const float* __restrict__ V, float* __restrict__ O)
{
    __shared__ float4 Ks[16][16];   // 16 keys x 64 floats
    __shared__ float4 Vs[16][16];

    const int tid  = threadIdx.x;
    const int bh   = blockIdx.y;
    const int b    = bh >> 4, h = bh & 15;
    const int row  = blockIdx.x * 128 + (tid >> 1);
    const int half = tid & 1;

    const size_t batchOff = (size_t)b * SS * DD;
    const float4* Kg = reinterpret_cast<const float4*>(K + batchOff + h * DKK);
    const float4* Vg = reinterpret_cast<const float4*>(V + batchOff + h * DKK);

    // q: 32 dims as 16 packed f32x2, pre-scaled by 1/8
    unsigned long long q2[16];
    {
        const float4* qp = reinterpret_cast<const float4*>(
            Q + batchOff + (size_t)row * DD + h * DKK + half * 32);
#pragma unroll
        for (int i = 0; i < 8; i++) {
            float4 t = qp[i];
            q2[2*i]   = pack2(t.x * 0.125f, t.y * 0.125f);
            q2[2*i+1] = pack2(t.z * 0.125f, t.w * 0.125f);
        }
    }
    unsigned long long o2[16];
#pragma unroll
    for (int i = 0; i < 16; i++) o2[i] = 0ull;
    float m = -1e30f, l = 0.f;

    const int lr = tid >> 4, lc = tid & 15;   // staging slot
    float4 pk = Kg[lr * 256 + lc];
    float4 pv = Vg[lr * 256 + lc];

#pragma unroll 1
    for (int t = 0; t < SS / 16; t++) {
        __syncthreads();
        Ks[lr][lc] = pk;
        Vs[lr][lc] = pv;
        __syncthreads();
        if (t < SS / 16 - 1) {
            pk = Kg[((t + 1) * 16 + lr) * 256 + lc];
            pv = Vg[((t + 1) * 16 + lr) * 256 + lc];
        }

        // scores (q pre-scaled)
        float s[16];
#pragma unroll
        for (int j = 0; j < 16; j++) {
            unsigned long long aa = 0ull, ab = 0ull;
            const double2* kp = reinterpret_cast<const double2*>(&Ks[j][half * 8]);
#pragma unroll
            for (int dd = 0; dd < 8; dd++) {
                double2 kv = kp[dd];
                FMA2(aa, q2[2*dd],   __double_as_longlong(kv.x));
                FMA2(ab, q2[2*dd+1], __double_as_longlong(kv.y));
            }
            float2 fa = unpack2(aa), fb = unpack2(ab);
            float part = (fa.x + fa.y) + (fb.x + fb.y);
            s[j] = part + __shfl_xor_sync(0xffffffffu, part, 1);
        }

        // online softmax
        float tmax = s[0];
#pragma unroll
        for (int j = 1; j < 16; j++) tmax = fmaxf(tmax, s[j]);
        float mn   = fmaxf(m, tmax);
        float corr = __expf(m - mn);
        m = mn;
        l *= corr;
        unsigned long long corr2 = pack2(corr, corr);
#pragma unroll
        for (int i = 0; i < 16; i++) MUL2(o2[i], o2[i], corr2);

#pragma unroll
        for (int j = 0; j < 16; j++) {
            float p = __expf(s[j] - mn);
            l += p;
            unsigned long long p2 = pack2(p, p);
            const double2* vp = reinterpret_cast<const double2*>(&Vs[j][half * 8]);
#pragma unroll
            for (int dd = 0; dd < 8; dd++) {
                double2 vv = vp[dd];
                FMA2(o2[2*dd],   p2, __double_as_longlong(vv.x));
                FMA2(o2[2*dd+1], p2, __double_as_longlong(vv.y));
            }
        }
    }

    // normalize + write
    float inv = 1.f / l;
    float4* op = reinterpret_cast<float4*>(
        O + batchOff + (size_t)row * DD + h * DKK + half * 32);
#pragma unroll
    for (int i = 0; i < 8; i++) {
        float2 a = unpack2(o2[2*i]), c = unpack2(o2[2*i+1]);
        op[i] = make_float4(a.x * inv, a.y * inv, c.x * inv, c.y * inv);
    }
}

// ---------------------------------------------------------------------------
// kernel_launch
// ---------------------------------------------------------------------------
extern "C" void kernel_launch(void* const* d_in, const int* in_sizes, int n_in,
                              void* d_out, int out_size)
{
    const float* query = (const float*)d_in[0];
    const float* key   = (const float*)d_in[1];
    const float* value = (const float*)d_in[2];
    const float* Wq    = (const float*)d_in[3];
    const float* bq    = (const float*)d_in[4];
    const float* Wk    = (const float*)d_in[5];
    const float* bk    = (const float*)d_in[6];
    const float* Wv    = (const float*)d_in[7];
    const float* bv    = (const float*)d_in[8];
    const float* Wo    = (const float*)d_in[9];
    const float* bo    = (const float*)d_in[10];
    float* out = (float*)d_out;

    float *qp, *kp, *vp, *ap;
    __nv_bfloat16 *ah, *al, *wh, *wl;
    cudaGetSymbolAddress((void**)&qp, g_q);
    cudaGetSymbolAddress((void**)&kp, g_k);
    cudaGetSymbolAddress((void**)&vp, g_v);
    cudaGetSymbolAddress((void**)&ap, g_att);
    cudaGetSymbolAddress((void**)&ah, g_ah);
    cudaGetSymbolAddress((void**)&al, g_al);
    cudaGetSymbolAddress((void**)&wh, g_wh);
    cudaGetSymbolAddress((void**)&wl, g_wl);

    cudaFuncSetAttribute(gemm_tc_kernel,
                         cudaFuncAttributeMaxDynamicSharedMemorySize, GEMM_SMEM);

    const int n4a = MROWS * DD / 4;
    const int n4w = DD * DD / 4;
    dim3 gGrid(DD / 128, MROWS / 128);   // (8, 64)

    // Q projection
    split_kernel<<<n4a / 256, 256>>>(query, ah, al, n4a);
    split_kernel<<<n4w / 256, 256>>>(Wq, wh, wl, n4w);
    gemm_tc_kernel<<<gGrid, 256, GEMM_SMEM>>>(ah, al, wh, wl, bq, qp);
    // K projection
    split_kernel<<<n4a / 256, 256>>>(key, ah, al, n4a);
    split_kernel<<<n4w / 256, 256>>>(Wk, wh, wl, n4w);
    gemm_tc_kernel<<<gGrid, 256, GEMM_SMEM>>>(ah, al, wh, wl, bk, kp);
    // V projection
    split_kernel<<<n4a / 256, 256>>>(value, ah, al, n4a);
    split_kernel<<<n4w / 256, 256>>>(Wv, wh, wl, n4w);
    gemm_tc_kernel<<<gGrid, 256, GEMM_SMEM>>>(ah, al, wh, wl, bv, vp);

    // Attention
    dim3 aGrid(SS / 128, BB * HH);       // (16, 64)
    attn_kernel<<<aGrid, 256>>>(qp, kp, vp, ap);

    // Output projection
    split_kernel<<<n4a / 256, 256>>>(ap, ah, al, n4a);
    split_kernel<<<n4w / 256, 256>>>(Wo, wh, wl, n4w);
    gemm_tc_kernel<<<gGrid, 256, GEMM_SMEM>>>(ah, al, wh, wl, bo, out);
}

// round 9
// speedup vs baseline: 1.0489x; 1.0010x over previous
#include <cuda_runtime.h>
#include <cuda_bf16.h>
#include <cstdint>

// Problem constants
#define BB 4
#define SS 2048
#define DD 1024
#define HH 16
#define DKK 64
#define MROWS (BB*SS)          // 8192

// ---------------------------------------------------------------------------
// Scratch (device globals — no allocations allowed)
// ---------------------------------------------------------------------------
__device__ float g_q[MROWS*DD];            // [B,S,D] fp32
__device__ float g_k[MROWS*DD];
__device__ float g_v[MROWS*DD];
__device__ float g_att[MROWS*DD];
__device__ __nv_bfloat16 g_ah[MROWS*DD];   // activation split hi/lo (reused per GEMM)
__device__ __nv_bfloat16 g_al[MROWS*DD];
__device__ __nv_bfloat16 g_wh[DD*DD];      // weight split hi/lo (reused per GEMM)
__device__ __nv_bfloat16 g_wl[DD*DD];

// ---------------------------------------------------------------------------
// Helpers
// ---------------------------------------------------------------------------
__device__ __forceinline__ uint32_t smem_u32(const void* p) {
    uint32_t a;
    asm("{ .reg .u64 t; cvta.to.shared.u64 t, %1; cvt.u32.u64 %0, t; }" : "=r"(a) : "l"(p));
    return a;
}
#define SWZ128(o) ((o) ^ (((o) >> 3) & 0x70))

#define CP_ASYNC16(dst, src) \
    asm volatile("cp.async.cg.shared.global [%0], [%1], 16;" :: "r"(dst), "l"(src))
#define CP_COMMIT()  asm volatile("cp.async.commit_group;" ::: "memory")
#define CP_WAIT0()   asm volatile("cp.async.wait_group 0;" ::: "memory")

__device__ __forceinline__ void ldsm_x4(uint32_t* r, uint32_t addr) {
    asm volatile("ldmatrix.sync.aligned.m8n8.x4.shared.b16 {%0,%1,%2,%3}, [%4];"
        : "=r"(r[0]), "=r"(r[1]), "=r"(r[2]), "=r"(r[3]) : "r"(addr));
}
__device__ __forceinline__ void ldsm_x2(uint32_t* r, uint32_t addr) {
    asm volatile("ldmatrix.sync.aligned.m8n8.x2.shared.b16 {%0,%1}, [%2];"
        : "=r"(r[0]), "=r"(r[1]) : "r"(addr));
}
__device__ __forceinline__ void mma16816(float* d, const uint32_t* a, const uint32_t* b) {
    asm volatile("mma.sync.aligned.m16n8k16.row.col.f32.bf16.bf16.f32 "
        "{%0,%1,%2,%3}, {%4,%5,%6,%7}, {%8,%9}, {%0,%1,%2,%3};"
        : "+f"(d[0]), "+f"(d[1]), "+f"(d[2]), "+f"(d[3])
        : "r"(a[0]), "r"(a[1]), "r"(a[2]), "r"(a[3]), "r"(b[0]), "r"(b[1]));
}

// packed f32x2 ops (sm_100-family base ISA, non-'a')
__device__ __forceinline__ unsigned long long pack2(float x, float y) {
    unsigned long long r; asm("mov.b64 %0, {%1, %2};" : "=l"(r) : "f"(x), "f"(y)); return r;
}
__device__ __forceinline__ float2 unpack2(unsigned long long v) {
    float2 f; asm("mov.b64 {%0, %1}, %2;" : "=f"(f.x), "=f"(f.y) : "l"(v)); return f;
}
#define FMA2(d, a, b) asm("fma.rn.f32x2 %0, %1, %2, %3;" : "=l"(d) : "l"(a), "l"(b), "l"(d))
#define MUL2(d, a, b) asm("mul.rn.f32x2 %0, %1, %2;"     : "=l"(d) : "l"(a), "l"(b))

// ---------------------------------------------------------------------------
// Split fp32 -> (bf16 hi, bf16 lo) with residual capture
// ---------------------------------------------------------------------------
__global__ __launch_bounds__(256) void split_kernel(
    const float* __restrict__ x, __nv_bfloat16* __restrict__ hi,
    __nv_bfloat16* __restrict__ lo, int n4)
{
    int i = blockIdx.x * 256 + threadIdx.x;
    if (i >= n4) return;
    float4 v = reinterpret_cast<const float4*>(x)[i];
    __nv_bfloat162 h0 = __floats2bfloat162_rn(v.x, v.y);
    __nv_bfloat162 h1 = __floats2bfloat162_rn(v.z, v.w);
    float r0 = v.x - __low2float(h0), r1 = v.y - __high2float(h0);
    float r2 = v.z - __low2float(h1), r3 = v.w - __high2float(h1);
    __nv_bfloat162* hp = reinterpret_cast<__nv_bfloat162*>(hi);
    __nv_bfloat162* lp = reinterpret_cast<__nv_bfloat162*>(lo);
    hp[2*i]   = h0;
    hp[2*i+1] = h1;
    lp[2*i]   = __floats2bfloat162_rn(r0, r1);
    lp[2*i+1] = __floats2bfloat162_rn(r2, r3);
}

// ---------------------------------------------------------------------------
// HMMA bf16x3 GEMM (NT): C[i,j] = sum_k A[i,k]*W[j,k] + bias[j]
// A=(Ah,Al) [M,K] bf16, W=(Bh,Bl) [N,K] bf16, fp32 register accumulators.
// CTA tile 128x128, K chunk 64 (SW128-swizzled 128B rows), cp.async
// double-buffered. 8 warps in 2(m) x 4(n); warp tile 64x32 via m16n8k16.
// ---------------------------------------------------------------------------
#define TILE_BYTES 16384               // 128 rows x 128B
#define BUF_BYTES  (4*TILE_BYTES)      // Ah,Al,Bh,Bl
#define GEMM_SMEM  (1024 + 2*BUF_BYTES)

__global__ __launch_bounds__(256, 1) void gemm_tc_kernel(
    const __nv_bfloat16* __restrict__ Ah, const __nv_bfloat16* __restrict__ Al,
    const __nv_bfloat16* __restrict__ Bh, const __nv_bfloat16* __restrict__ Bl,
    const float* __restrict__ bias, float* __restrict__ C)
{
    extern __shared__ char smem[];
    const uint32_t sbase = (smem_u32(smem) + 1023u) & ~1023u;
    const int tid = threadIdx.x;
    const int wid = tid >> 5;
    const int lid = tid & 31;
    const int wm  = wid >> 2;          // 0..1
    const int wn  = wid & 3;           // 0..3
    const int nBase = blockIdx.x * 128;
    const int mBase = blockIdx.y * 128;

    // Source bases in uint4 units (row stride = 1024 bf16 = 128 uint4)
    const uint4* srcs[4] = {
        reinterpret_cast<const uint4*>(Ah) + (size_t)mBase * 128,
        reinterpret_cast<const uint4*>(Al) + (size_t)mBase * 128,
        reinterpret_cast<const uint4*>(Bh) + (size_t)nBase * 128,
        reinterpret_cast<const uint4*>(Bl) + (size_t)nBase * 128
    };

    // Issue cp.async for one K-chunk (64 bf16) into buffer `buf`
    auto load_chunk = [&](int ch, int buf) {
        const int kq = ch * 8;         // k offset in uint4 units
        const uint32_t bufAddr = sbase + buf * BUF_BYTES;
#pragma unroll
        for (int t = 0; t < 16; t++) {
            const int tile = t >> 2;
            const int i = tid + (t & 3) * 256;   // 0..1023
            const int r = i >> 3, c = i & 7;
            const uint4* src = srcs[tile] + (size_t)r * 128 + kq + c;
            uint32_t dst = bufAddr + tile * TILE_BYTES + SWZ128(r * 128 + c * 16);
            CP_ASYNC16(dst, src);
        }
        CP_COMMIT();
    };

    float acc[4][4][4];
#pragma unroll
    for (int mt = 0; mt < 4; mt++)
#pragma unroll
        for (int nt = 0; nt < 4; nt++)
#pragma unroll
            for (int r = 0; r < 4; r++) acc[mt][nt][r] = 0.f;

    load_chunk(0, 0);
    CP_WAIT0();
    __syncthreads();

    // fragment address components (per-thread, chunk-invariant)
    const int aRow = wm * 64 + (lid & 15);
    const int aColH = (lid >> 4) * 16;           // 0 or 16 bytes
    const int bRow = wn * 32 + (lid & 7);
    const int bColH = ((lid >> 3) & 1) * 16;

#pragma unroll 1
    for (int ch = 0; ch < 16; ch++) {
        const int cur = ch & 1;
        if (ch < 15) load_chunk(ch + 1, cur ^ 1);

        const uint32_t bufAddr = sbase + cur * BUF_BYTES;
        const uint32_t aH = bufAddr;
        const uint32_t aL = bufAddr + TILE_BYTES;
        const uint32_t bH = bufAddr + 2 * TILE_BYTES;
        const uint32_t bL = bufAddr + 3 * TILE_BYTES;

#pragma unroll
        for (int ks = 0; ks < 4; ks++) {
            const int kByte = ks * 32;
            uint32_t ah[4][4], al[4][4], bh[4][2], bl[4][2];
#pragma unroll
            for (int mt = 0; mt < 4; mt++) {
                uint32_t off = SWZ128((aRow + mt * 16) * 128 + kByte + aColH);
                ldsm_x4(ah[mt], aH + off);
                ldsm_x4(al[mt], aL + off);
            }
#pragma unroll
            for (int nt = 0; nt < 4; nt++) {
                uint32_t off = SWZ128((bRow + nt * 8) * 128 + kByte + bColH);
                ldsm_x2(bh[nt], bH + off);
                ldsm_x2(bl[nt], bL + off);
            }
#pragma unroll
            for (int mt = 0; mt < 4; mt++)
#pragma unroll
                for (int nt = 0; nt < 4; nt++) {
                    mma16816(acc[mt][nt], ah[mt], bh[nt]);
                    mma16816(acc[mt][nt], ah[mt], bl[nt]);
                    mma16816(acc[mt][nt], al[mt], bh[nt]);
                }
        }

        if (ch < 15) CP_WAIT0();
        __syncthreads();
    }

    // Epilogue: direct global write with bias
    const int erow = mBase + wm * 64 + (lid >> 2);
    const int ecolBase = nBase + wn * 32 + 2 * (lid & 3);
#pragma unroll
    for (int nt = 0; nt < 4; nt++) {
        const int col = ecolBase + nt * 8;
        const float b0 = __ldg(bias + col), b1 = __ldg(bias + col + 1);
#pragma unroll
        for (int mt = 0; mt < 4; mt++) {
            const int r0 = erow + mt * 16;
            float2 v0 = make_float2(acc[mt][nt][0] + b0, acc[mt][nt][1] + b1);
            float2 v1 = make_float2(acc[mt][nt][2] + b0, acc[mt][nt][3] + b1);
            *reinterpret_cast<float2*>(C + (size_t)r0 * DD + col)       = v0;
            *reinterpret_cast<float2*>(C + (size_t)(r0 + 8) * DD + col) = v1;
        }
    }
}

// ---------------------------------------------------------------------------
// Flash attention with packed f32x2 FMA. Q,K,V,O all [B,S,D] fp32; head h
// occupies column block h*64..h*64+63. Two threads per query row (32 dims
// each), shfl_xor(1) combines score partials. Register-prefetched K/V tiles.
// ---------------------------------------------------------------------------
__global__ __launch_bounds__(256, 2) void attn_kernel(
    const float* __restrict__ Q, const float* __restrict__ K,
    const float* __restrict__ V, float* __restrict__ O)
{
    __shared__ float4 Ks[16][16];   // 16 keys x 64 floats
    __shared__ float4 Vs[16][16];

    const int tid  = threadIdx.x;
    const int bh   = blockIdx.y;
    const int b    = bh >> 4, h = bh & 15;
    const int row  = blockIdx.x * 128 + (tid >> 1);
    const int half = tid & 1;

    const size_t batchOff = (size_t)b * SS * DD;
    const float4* Kg = reinterpret_cast<const float4*>(K + batchOff + h * DKK);
    const float4* Vg = reinterpret_cast<const float4*>(V + batchOff + h * DKK);

    // q: 32 dims as 16 packed f32x2, pre-scaled by 1/8
    unsigned long long q2[16];
    {
        const float4* qp = reinterpret_cast<const float4*>(
            Q + batchOff + (size_t)row * DD + h * DKK + half * 32);
#pragma unroll
        for (int i = 0; i < 8; i++) {
            float4 t = qp[i];
            q2[2*i]   = pack2(t.x * 0.125f, t.y * 0.125f);
            q2[2*i+1] = pack2(t.z * 0.125f, t.w * 0.125f);
        }
    }
    unsigned long long o2[16];
#pragma unroll
    for (int i = 0; i < 16; i++) o2[i] = 0ull;
    float m = -1e30f, l = 0.f;

    const int lr = tid >> 4, lc = tid & 15;   // staging slot
    float4 pk = Kg[lr * 256 + lc];
    float4 pv = Vg[lr * 256 + lc];

#pragma unroll 1
    for (int t = 0; t < SS / 16; t++) {
        __syncthreads();
        Ks[lr][lc] = pk;
        Vs[lr][lc] = pv;
        __syncthreads();
        if (t < SS / 16 - 1) {
            pk = Kg[((t + 1) * 16 + lr) * 256 + lc];
            pv = Vg[((t + 1) * 16 + lr) * 256 + lc];
        }

        // scores (q pre-scaled)
        float s[16];
#pragma unroll
        for (int j = 0; j < 16; j++) {
            unsigned long long aa = 0ull, ab = 0ull;
            const double2* kp = reinterpret_cast<const double2*>(&Ks[j][half * 8]);
#pragma unroll
            for (int dd = 0; dd < 8; dd++) {
                double2 kv = kp[dd];
                FMA2(aa, q2[2*dd],   __double_as_longlong(kv.x));
                FMA2(ab, q2[2*dd+1], __double_as_longlong(kv.y));
            }
            float2 fa = unpack2(aa), fb = unpack2(ab);
            float part = (fa.x + fa.y) + (fb.x + fb.y);
            s[j] = part + __shfl_xor_sync(0xffffffffu, part, 1);
        }

        // online softmax
        float tmax = s[0];
#pragma unroll
        for (int j = 1; j < 16; j++) tmax = fmaxf(tmax, s[j]);
        float mn   = fmaxf(m, tmax);
        float corr = __expf(m - mn);
        m = mn;
        l *= corr;
        unsigned long long corr2 = pack2(corr, corr);
#pragma unroll
        for (int i = 0; i < 16; i++) MUL2(o2[i], o2[i], corr2);

#pragma unroll
        for (int j = 0; j < 16; j++) {
            float p = __expf(s[j] - mn);
            l += p;
            unsigned long long p2 = pack2(p, p);
            const double2* vp = reinterpret_cast<const double2*>(&Vs[j][half * 8]);
#pragma unroll
            for (int dd = 0; dd < 8; dd++) {
                double2 vv = vp[dd];
                FMA2(o2[2*dd],   p2, __double_as_longlong(vv.x));
                FMA2(o2[2*dd+1], p2, __double_as_longlong(vv.y));
            }
        }
    }

    // normalize + write
    float inv = 1.f / l;
    float4* op = reinterpret_cast<float4*>(
        O + batchOff + (size_t)row * DD + h * DKK + half * 32);
#pragma unroll
    for (int i = 0; i < 8; i++) {
        float2 a = unpack2(o2[2*i]), c = unpack2(o2[2*i+1]);
        op[i] = make_float4(a.x * inv, a.y * inv, c.x * inv, c.y * inv);
    }
}

// ---------------------------------------------------------------------------
// kernel_launch
// ---------------------------------------------------------------------------
extern "C" void kernel_launch(void* const* d_in, const int* in_sizes, int n_in,
                              void* d_out, int out_size)
{
    const float* query = (const float*)d_in[0];
    const float* key   = (const float*)d_in[1];
    const float* value = (const float*)d_in[2];
    const float* Wq    = (const float*)d_in[3];
    const float* bq    = (const float*)d_in[4];
    const float* Wk    = (const float*)d_in[5];
    const float* bk    = (const float*)d_in[6];
    const float* Wv    = (const float*)d_in[7];
    const float* bv    = (const float*)d_in[8];
    const float* Wo    = (const float*)d_in[9];
    const float* bo    = (const float*)d_in[10];
    float* out = (float*)d_out;

    float *qp, *kp, *vp, *ap;
    __nv_bfloat16 *ah, *al, *wh, *wl;
    cudaGetSymbolAddress((void**)&qp, g_q);
    cudaGetSymbolAddress((void**)&kp, g_k);
    cudaGetSymbolAddress((void**)&vp, g_v);
    cudaGetSymbolAddress((void**)&ap, g_att);
    cudaGetSymbolAddress((void**)&ah, g_ah);
    cudaGetSymbolAddress((void**)&al, g_al);
    cudaGetSymbolAddress((void**)&wh, g_wh);
    cudaGetSymbolAddress((void**)&wl, g_wl);

    cudaFuncSetAttribute(gemm_tc_kernel,
                         cudaFuncAttributeMaxDynamicSharedMemorySize, GEMM_SMEM);

    const int n4a = MROWS * DD / 4;
    const int n4w = DD * DD / 4;
    dim3 gGrid(DD / 128, MROWS / 128);   // (8, 64)

    // Q projection
    split_kernel<<<n4a / 256, 256>>>(query, ah, al, n4a);
    split_kernel<<<n4w / 256, 256>>>(Wq, wh, wl, n4w);
    gemm_tc_kernel<<<gGrid, 256, GEMM_SMEM>>>(ah, al, wh, wl, bq, qp);
    // K projection
    split_kernel<<<n4a / 256, 256>>>(key, ah, al, n4a);
    split_kernel<<<n4w / 256, 256>>>(Wk, wh, wl, n4w);
    gemm_tc_kernel<<<gGrid, 256, GEMM_SMEM>>>(ah, al, wh, wl, bk, kp);
    // V projection
    split_kernel<<<n4a / 256, 256>>>(value, ah, al, n4a);
    split_kernel<<<n4w / 256, 256>>>(Wv, wh, wl, n4w);
    gemm_tc_kernel<<<gGrid, 256, GEMM_SMEM>>>(ah, al, wh, wl, bv, vp);

    // Attention
    dim3 aGrid(SS / 128, BB * HH);       // (16, 64)
    attn_kernel<<<aGrid, 256>>>(qp, kp, vp, ap);

    // Output projection
    split_kernel<<<n4a / 256, 256>>>(ap, ah, al, n4a);
    split_kernel<<<n4w / 256, 256>>>(Wo, wh, wl, n4w);
    gemm_tc_kernel<<<gGrid, 256, GEMM_SMEM>>>(ah, al, wh, wl, bo, out);
}

// round 10
// speedup vs baseline: 3.9900x; 3.8039x over previous
#include <cuda_runtime.h>
#include <cuda_bf16.h>
#include <cstdint>

// Problem constants
#define BB 4
#define SS 2048
#define DD 1024
#define HH 16
#define DKK 64
#define MROWS (BB*SS)          // 8192

// ---------------------------------------------------------------------------
// Scratch (device globals — no allocations allowed)
// ---------------------------------------------------------------------------
__device__ __nv_bfloat16 g_qh[MROWS*DD], g_ql[MROWS*DD];   // Q proj out (pre-scaled 1/8)
__device__ __nv_bfloat16 g_kh[MROWS*DD], g_kl[MROWS*DD];   // K proj out
__device__ __nv_bfloat16 g_vh[MROWS*DD], g_vl[MROWS*DD];   // V proj out
__device__ __nv_bfloat16 g_ah[MROWS*DD], g_al[MROWS*DD];   // GEMM-A splits / attn out
__device__ __nv_bfloat16 g_wh[DD*DD],   g_wl[DD*DD];       // weight splits

// ---------------------------------------------------------------------------
// Helpers
// ---------------------------------------------------------------------------
__device__ __forceinline__ uint32_t smem_u32(const void* p) {
    uint32_t a;
    asm("{ .reg .u64 t; cvta.to.shared.u64 t, %1; cvt.u32.u64 %0, t; }" : "=r"(a) : "l"(p));
    return a;
}
#define SWZ128(o) ((o) ^ (((o) >> 3) & 0x70))

#define CP_ASYNC16(dst, src) \
    asm volatile("cp.async.cg.shared.global [%0], [%1], 16;" :: "r"(dst), "l"(src))
#define CP_COMMIT()  asm volatile("cp.async.commit_group;" ::: "memory")
#define CP_WAIT0()   asm volatile("cp.async.wait_group 0;" ::: "memory")

__device__ __forceinline__ void ldsm_x4(uint32_t* r, uint32_t addr) {
    asm volatile("ldmatrix.sync.aligned.m8n8.x4.shared.b16 {%0,%1,%2,%3}, [%4];"
        : "=r"(r[0]), "=r"(r[1]), "=r"(r[2]), "=r"(r[3]) : "r"(addr));
}
__device__ __forceinline__ void ldsm_x2(uint32_t* r, uint32_t addr) {
    asm volatile("ldmatrix.sync.aligned.m8n8.x2.shared.b16 {%0,%1}, [%2];"
        : "=r"(r[0]), "=r"(r[1]) : "r"(addr));
}
__device__ __forceinline__ void ldsm_x2t(uint32_t* r, uint32_t addr) {
    asm volatile("ldmatrix.sync.aligned.m8n8.x2.trans.shared.b16 {%0,%1}, [%2];"
        : "=r"(r[0]), "=r"(r[1]) : "r"(addr));
}
__device__ __forceinline__ void mma16816(float* d, const uint32_t* a, const uint32_t* b) {
    asm volatile("mma.sync.aligned.m16n8k16.row.col.f32.bf16.bf16.f32 "
        "{%0,%1,%2,%3}, {%4,%5,%6,%7}, {%8,%9}, {%0,%1,%2,%3};"
        : "+f"(d[0]), "+f"(d[1]), "+f"(d[2]), "+f"(d[3])
        : "r"(a[0]), "r"(a[1]), "r"(a[2]), "r"(a[3]), "r"(b[0]), "r"(b[1]));
}
__device__ __forceinline__ uint32_t packbf2(float x, float y) {
    __nv_bfloat162 t = __floats2bfloat162_rn(x, y);
    return *reinterpret_cast<uint32_t*>(&t);
}

// ---------------------------------------------------------------------------
// Split fp32 -> (bf16 hi, bf16 lo) with residual capture
// ---------------------------------------------------------------------------
__global__ __launch_bounds__(256) void split_kernel(
    const float* __restrict__ x, __nv_bfloat16* __restrict__ hi,
    __nv_bfloat16* __restrict__ lo, int n4)
{
    int i = blockIdx.x * 256 + threadIdx.x;
    if (i >= n4) return;
    float4 v = reinterpret_cast<const float4*>(x)[i];
    __nv_bfloat162 h0 = __floats2bfloat162_rn(v.x, v.y);
    __nv_bfloat162 h1 = __floats2bfloat162_rn(v.z, v.w);
    float r0 = v.x - __low2float(h0), r1 = v.y - __high2float(h0);
    float r2 = v.z - __low2float(h1), r3 = v.w - __high2float(h1);
    __nv_bfloat162* hp = reinterpret_cast<__nv_bfloat162*>(hi);
    __nv_bfloat162* lp = reinterpret_cast<__nv_bfloat162*>(lo);
    hp[2*i]   = h0;
    hp[2*i+1] = h1;
    lp[2*i]   = __floats2bfloat162_rn(r0, r1);
    lp[2*i+1] = __floats2bfloat162_rn(r2, r3);
}

// ---------------------------------------------------------------------------
// HMMA bf16x3 GEMM (NT): acc = sum_k A[i,k]*W[j,k]; out = (acc + bias[j])*scale
// Output either fp32 C, or bf16 hi/lo pair (Ch,Cl).
// CTA tile 128x128, K chunk 64, SW128 smem, cp.async double-buffered.
// 8 warps in 2(m) x 4(n); warp tile 64x32 via m16n8k16.
// ---------------------------------------------------------------------------
#define TILE_BYTES 16384               // 128 rows x 128B
#define BUF_BYTES  (4*TILE_BYTES)      // Ah,Al,Bh,Bl
#define GEMM_SMEM  (1024 + 2*BUF_BYTES)

__global__ __launch_bounds__(256, 1) void gemm_tc_kernel(
    const __nv_bfloat16* __restrict__ Ah, const __nv_bfloat16* __restrict__ Al,
    const __nv_bfloat16* __restrict__ Bh, const __nv_bfloat16* __restrict__ Bl,
    const float* __restrict__ bias, float* __restrict__ C,
    __nv_bfloat16* __restrict__ Ch, __nv_bfloat16* __restrict__ Cl, float scale)
{
    extern __shared__ char smem[];
    const uint32_t sbase = (smem_u32(smem) + 1023u) & ~1023u;
    const int tid = threadIdx.x;
    const int wid = tid >> 5;
    const int lid = tid & 31;
    const int wm  = wid >> 2;          // 0..1
    const int wn  = wid & 3;           // 0..3
    const int nBase = blockIdx.x * 128;
    const int mBase = blockIdx.y * 128;

    const uint4* srcs[4] = {
        reinterpret_cast<const uint4*>(Ah) + (size_t)mBase * 128,
        reinterpret_cast<const uint4*>(Al) + (size_t)mBase * 128,
        reinterpret_cast<const uint4*>(Bh) + (size_t)nBase * 128,
        reinterpret_cast<const uint4*>(Bl) + (size_t)nBase * 128
    };

    auto load_chunk = [&](int ch, int buf) {
        const int kq = ch * 8;
        const uint32_t bufAddr = sbase + buf * BUF_BYTES;
#pragma unroll
        for (int t = 0; t < 16; t++) {
            const int tile = t >> 2;
            const int i = tid + (t & 3) * 256;
            const int r = i >> 3, c = i & 7;
            const uint4* src = srcs[tile] + (size_t)r * 128 + kq + c;
            uint32_t dst = bufAddr + tile * TILE_BYTES + SWZ128(r * 128 + c * 16);
            CP_ASYNC16(dst, src);
        }
        CP_COMMIT();
    };

    float acc[4][4][4];
#pragma unroll
    for (int mt = 0; mt < 4; mt++)
#pragma unroll
        for (int nt = 0; nt < 4; nt++)
#pragma unroll
            for (int r = 0; r < 4; r++) acc[mt][nt][r] = 0.f;

    load_chunk(0, 0);
    CP_WAIT0();
    __syncthreads();

    const int aRow = wm * 64 + (lid & 15);
    const int aColH = (lid >> 4) * 16;
    const int bRow = wn * 32 + (lid & 7);
    const int bColH = ((lid >> 3) & 1) * 16;

#pragma unroll 1
    for (int ch = 0; ch < 16; ch++) {
        const int cur = ch & 1;
        if (ch < 15) load_chunk(ch + 1, cur ^ 1);

        const uint32_t bufAddr = sbase + cur * BUF_BYTES;
        const uint32_t aH = bufAddr;
        const uint32_t aL = bufAddr + TILE_BYTES;
        const uint32_t bH = bufAddr + 2 * TILE_BYTES;
        const uint32_t bL = bufAddr + 3 * TILE_BYTES;

#pragma unroll
        for (int ks = 0; ks < 4; ks++) {
            const int kByte = ks * 32;
            uint32_t ah[4][4], al[4][4], bh[4][2], bl[4][2];
#pragma unroll
            for (int mt = 0; mt < 4; mt++) {
                uint32_t off = SWZ128((aRow + mt * 16) * 128 + kByte + aColH);
                ldsm_x4(ah[mt], aH + off);
                ldsm_x4(al[mt], aL + off);
            }
#pragma unroll
            for (int nt = 0; nt < 4; nt++) {
                uint32_t off = SWZ128((bRow + nt * 8) * 128 + kByte + bColH);
                ldsm_x2(bh[nt], bH + off);
                ldsm_x2(bl[nt], bL + off);
            }
#pragma unroll
            for (int mt = 0; mt < 4; mt++)
#pragma unroll
                for (int nt = 0; nt < 4; nt++) {
                    mma16816(acc[mt][nt], ah[mt], bh[nt]);
                    mma16816(acc[mt][nt], ah[mt], bl[nt]);
                    mma16816(acc[mt][nt], al[mt], bh[nt]);
                }
        }

        if (ch < 15) CP_WAIT0();
        __syncthreads();
    }

    // Epilogue
    const int erow = mBase + wm * 64 + (lid >> 2);
    const int ecolBase = nBase + wn * 32 + 2 * (lid & 3);
#pragma unroll
    for (int nt = 0; nt < 4; nt++) {
        const int col = ecolBase + nt * 8;
        const float b0 = __ldg(bias + col), b1 = __ldg(bias + col + 1);
#pragma unroll
        for (int mt = 0; mt < 4; mt++) {
            const int r0 = erow + mt * 16;
            float v0 = (acc[mt][nt][0] + b0) * scale;
            float v1 = (acc[mt][nt][1] + b1) * scale;
            float v2 = (acc[mt][nt][2] + b0) * scale;
            float v3 = (acc[mt][nt][3] + b1) * scale;
            if (C) {
                *reinterpret_cast<float2*>(C + (size_t)r0 * DD + col)       = make_float2(v0, v1);
                *reinterpret_cast<float2*>(C + (size_t)(r0 + 8) * DD + col) = make_float2(v2, v3);
            } else {
                __nv_bfloat162 h0 = __floats2bfloat162_rn(v0, v1);
                __nv_bfloat162 h1 = __floats2bfloat162_rn(v2, v3);
                *reinterpret_cast<__nv_bfloat162*>(Ch + (size_t)r0 * DD + col)       = h0;
                *reinterpret_cast<__nv_bfloat162*>(Ch + (size_t)(r0 + 8) * DD + col) = h1;
                *reinterpret_cast<__nv_bfloat162*>(Cl + (size_t)r0 * DD + col) =
                    __floats2bfloat162_rn(v0 - __low2float(h0), v1 - __high2float(h0));
                *reinterpret_cast<__nv_bfloat162*>(Cl + (size_t)(r0 + 8) * DD + col) =
                    __floats2bfloat162_rn(v2 - __low2float(h1), v3 - __high2float(h1));
            }
        }
    }
}

// ---------------------------------------------------------------------------
// MMA flash attention. Q pre-scaled by 1/8. All operands bf16 hi/lo in
// [B,S,D] layout (head h = cols h*64..+63). Output -> (Oh,Ol) bf16 hi/lo.
// CTA: 128 query rows x one (b,h); 8 warps x 16 rows; BK=32 keys/iter.
// scores = Qh*Kh + Qh*Kl + Ql*Kh ; PV = Ph*Vh + Ph*Vl + Pl*Vh (fp32 acc).
// P A-fragments come directly from score accumulators (layout identity).
// ---------------------------------------------------------------------------
#define KV_BYTES 16384                 // Kh,Kl,Vh,Vl 32x128B each
#define ATT_SMEM (32768 + 2*KV_BYTES + 1024)

__global__ __launch_bounds__(256, 2) void attn_mma_kernel(
    const __nv_bfloat16* __restrict__ Qh, const __nv_bfloat16* __restrict__ Ql,
    const __nv_bfloat16* __restrict__ Kh, const __nv_bfloat16* __restrict__ Kl,
    const __nv_bfloat16* __restrict__ Vh, const __nv_bfloat16* __restrict__ Vl,
    __nv_bfloat16* __restrict__ Oh, __nv_bfloat16* __restrict__ Ol)
{
    extern __shared__ char smem[];
    const uint32_t sb = (smem_u32(smem) + 1023u) & ~1023u;
    const int tid = threadIdx.x;
    const int wid = tid >> 5;
    const int lid = tid & 31;
    const int bh  = blockIdx.y;
    const int b   = bh >> 4, h = bh & 15;
    const int qBase = blockIdx.x * 128;

    const uint32_t QH_OFF = 0, QL_OFF = 16384, KV_OFF = 32768;
    const size_t qOrg = (size_t)(b * SS + qBase) * DD + h * DKK;   // Q tile origin (elems)
    const size_t kOrg = (size_t)(b * SS) * DD + h * DKK;           // K/V batch origin

    // ---- stage Q (hi/lo) : 2 x 128 rows x 8 chunks of 16B ----
    {
        const int idx = tid & 1023;        // placeholder to keep pattern clear
        (void)idx;
#pragma unroll
        for (int j = 0; j < 8; j++) {
            int i  = tid + j * 256;        // 0..2047
            int sp = i >> 10;              // 0=hi 1=lo
            int r  = (i & 1023) >> 3;
            int c  = i & 7;
            const __nv_bfloat16* src = (sp ? Ql : Qh) + qOrg + (size_t)r * DD + c * 8;
            uint32_t dst = sb + (sp ? QL_OFF : QH_OFF) + SWZ128(r * 128 + c * 16);
            CP_ASYNC16(dst, src);
        }
    }
    // ---- K/V tile loader: 32 keys x 64 dims, 4 tiles (Kh,Kl,Vh,Vl) ----
    const __nv_bfloat16* kvsrc[4] = { Kh, Kl, Vh, Vl };
    auto load_kv = [&](int t, int buf) {
        const int r = tid >> 3, c = tid & 7;             // r 0..31, c 0..7
        const size_t g = kOrg + (size_t)(t * 32 + r) * DD + c * 8;
        const uint32_t dstb = sb + KV_OFF + buf * KV_BYTES + SWZ128(r * 128 + c * 16);
#pragma unroll
        for (int tile = 0; tile < 4; tile++)
            CP_ASYNC16(dstb + tile * 4096, kvsrc[tile] + g);
        CP_COMMIT();
    };

    load_kv(0, 0);
    CP_WAIT0();
    __syncthreads();

    // ---- Q fragments (held in regs for whole kernel) ----
    uint32_t qfh[4][4], qfl[4][4];
    {
        const int aRow = wid * 16 + (lid & 15);
        const int aColH = (lid >> 4) * 16;
#pragma unroll
        for (int ks = 0; ks < 4; ks++) {
            uint32_t off = SWZ128(aRow * 128 + ks * 32 + aColH);
            ldsm_x4(qfh[ks], sb + QH_OFF + off);
            ldsm_x4(qfl[ks], sb + QL_OFF + off);
        }
    }

    float o[8][4];
#pragma unroll
    for (int nt = 0; nt < 8; nt++)
#pragma unroll
        for (int r = 0; r < 4; r++) o[nt][r] = 0.f;
    float m0 = -1e30f, m1 = -1e30f, l0 = 0.f, l1 = 0.f;

    // fragment address components
    const uint32_t kFragBase = (lid & 7) * 128 + ((lid >> 3) & 1) * 16;       // + nt*1024 + ks*32
    const uint32_t vFragRow  = ((lid & 7) + 8 * ((lid >> 3) & 1)) * 128;      // + ks*2048 + nt*16

#pragma unroll 1
    for (int t = 0; t < SS / 32; t++) {
        const int cur = t & 1;
        if (t < SS / 32 - 1) load_kv(t + 1, cur ^ 1);

        const uint32_t kb = sb + KV_OFF + cur * KV_BYTES;

        // ---- scores: m16 x n32 x k64, bf16x3 ----
        float s[4][4];
#pragma unroll
        for (int nt = 0; nt < 4; nt++)
#pragma unroll
            for (int r = 0; r < 4; r++) s[nt][r] = 0.f;
#pragma unroll
        for (int ks = 0; ks < 4; ks++) {
#pragma unroll
            for (int nt = 0; nt < 4; nt++) {
                uint32_t kbh[2], kbl[2];
                uint32_t off = SWZ128(nt * 1024 + kFragBase + ks * 32);
                ldsm_x2(kbh, kb + off);            // Kh tile @ +0
                ldsm_x2(kbl, kb + 4096 + off);     // Kl tile
                mma16816(s[nt], qfh[ks], kbh);
                mma16816(s[nt], qfh[ks], kbl);
                mma16816(s[nt], qfl[ks], kbh);
            }
        }

        // ---- online softmax (rows r=lid>>2 and r+8; cols across lanes lid&3) ----
        float t0 = -1e30f, t1 = -1e30f;
#pragma unroll
        for (int nt = 0; nt < 4; nt++) {
            t0 = fmaxf(t0, fmaxf(s[nt][0], s[nt][1]));
            t1 = fmaxf(t1, fmaxf(s[nt][2], s[nt][3]));
        }
        t0 = fmaxf(t0, __shfl_xor_sync(0xffffffffu, t0, 1));
        t0 = fmaxf(t0, __shfl_xor_sync(0xffffffffu, t0, 2));
        t1 = fmaxf(t1, __shfl_xor_sync(0xffffffffu, t1, 1));
        t1 = fmaxf(t1, __shfl_xor_sync(0xffffffffu, t1, 2));
        const float mn0 = fmaxf(m0, t0), mn1 = fmaxf(m1, t1);
        const float c0 = __expf(m0 - mn0), c1 = __expf(m1 - mn1);
        m0 = mn0; m1 = mn1;

        uint32_t aPh[2][4], aPl[2][4];
        float rs0 = 0.f, rs1 = 0.f;
#pragma unroll
        for (int nt = 0; nt < 4; nt++) {
            float p0 = __expf(s[nt][0] - m0);
            float p1 = __expf(s[nt][1] - m0);
            float p2 = __expf(s[nt][2] - m1);
            float p3 = __expf(s[nt][3] - m1);
            rs0 += p0 + p1; rs1 += p2 + p3;
            const int ks = nt >> 1, pos = (nt & 1) * 2;
            __nv_bfloat162 hA = __floats2bfloat162_rn(p0, p1);
            __nv_bfloat162 hB = __floats2bfloat162_rn(p2, p3);
            aPh[ks][pos]     = *reinterpret_cast<uint32_t*>(&hA);
            aPh[ks][pos + 1] = *reinterpret_cast<uint32_t*>(&hB);
            aPl[ks][pos]     = packbf2(p0 - __low2float(hA), p1 - __high2float(hA));
            aPl[ks][pos + 1] = packbf2(p2 - __low2float(hB), p3 - __high2float(hB));
        }
        rs0 += __shfl_xor_sync(0xffffffffu, rs0, 1);
        rs0 += __shfl_xor_sync(0xffffffffu, rs0, 2);
        rs1 += __shfl_xor_sync(0xffffffffu, rs1, 1);
        rs1 += __shfl_xor_sync(0xffffffffu, rs1, 2);
        l0 = l0 * c0 + rs0;
        l1 = l1 * c1 + rs1;

#pragma unroll
        for (int nt = 0; nt < 8; nt++) {
            o[nt][0] *= c0; o[nt][1] *= c0;
            o[nt][2] *= c1; o[nt][3] *= c1;
        }

        // ---- PV: m16 x n64 x k32, bf16x3 (V via ldmatrix.trans) ----
#pragma unroll
        for (int ks = 0; ks < 2; ks++) {
#pragma unroll
            for (int nt = 0; nt < 8; nt++) {
                uint32_t vbh[2], vbl[2];
                uint32_t off = SWZ128(ks * 2048 + vFragRow + nt * 16);
                ldsm_x2t(vbh, kb + 8192 + off);     // Vh tile
                ldsm_x2t(vbl, kb + 12288 + off);    // Vl tile
                mma16816(o[nt], aPh[ks], vbh);
                mma16816(o[nt], aPh[ks], vbl);
                mma16816(o[nt], aPl[ks], vbh);
            }
        }

        CP_WAIT0();
        __syncthreads();
    }

    // ---- epilogue: normalize, split to bf16 hi/lo, write [B,S,D] ----
    const float i0 = 1.f / l0, i1 = 1.f / l1;
    const size_t row0 = (size_t)(b * SS + qBase + wid * 16 + (lid >> 2));
    const int colBase = h * DKK + 2 * (lid & 3);
#pragma unroll
    for (int nt = 0; nt < 8; nt++) {
        const int col = colBase + nt * 8;
        float v0 = o[nt][0] * i0, v1 = o[nt][1] * i0;
        float v2 = o[nt][2] * i1, v3 = o[nt][3] * i1;
        __nv_bfloat162 h0 = __floats2bfloat162_rn(v0, v1);
        __nv_bfloat162 h1 = __floats2bfloat162_rn(v2, v3);
        *reinterpret_cast<__nv_bfloat162*>(Oh + row0 * DD + col)       = h0;
        *reinterpret_cast<__nv_bfloat162*>(Oh + (row0 + 8) * DD + col) = h1;
        *reinterpret_cast<__nv_bfloat162*>(Ol + row0 * DD + col) =
            __floats2bfloat162_rn(v0 - __low2float(h0), v1 - __high2float(h0));
        *reinterpret_cast<__nv_bfloat162*>(Ol + (row0 + 8) * DD + col) =
            __floats2bfloat162_rn(v2 - __low2float(h1), v3 - __high2float(h1));
    }
}

// ---------------------------------------------------------------------------
// kernel_launch
// ---------------------------------------------------------------------------
extern "C" void kernel_launch(void* const* d_in, const int* in_sizes, int n_in,
                              void* d_out, int out_size)
{
    const float* query = (const float*)d_in[0];
    const float* key   = (const float*)d_in[1];
    const float* value = (const float*)d_in[2];
    const float* Wq    = (const float*)d_in[3];
    const float* bq    = (const float*)d_in[4];
    const float* Wk    = (const float*)d_in[5];
    const float* bk    = (const float*)d_in[6];
    const float* Wv    = (const float*)d_in[7];
    const float* bv    = (const float*)d_in[8];
    const float* Wo    = (const float*)d_in[9];
    const float* bo    = (const float*)d_in[10];
    float* out = (float*)d_out;

    __nv_bfloat16 *qh, *ql, *kh, *kl, *vh, *vl, *ah, *al, *wh, *wl;
    cudaGetSymbolAddress((void**)&qh, g_qh);
    cudaGetSymbolAddress((void**)&ql, g_ql);
    cudaGetSymbolAddress((void**)&kh, g_kh);
    cudaGetSymbolAddress((void**)&kl, g_kl);
    cudaGetSymbolAddress((void**)&vh, g_vh);
    cudaGetSymbolAddress((void**)&vl, g_vl);
    cudaGetSymbolAddress((void**)&ah, g_ah);
    cudaGetSymbolAddress((void**)&al, g_al);
    cudaGetSymbolAddress((void**)&wh, g_wh);
    cudaGetSymbolAddress((void**)&wl, g_wl);

    cudaFuncSetAttribute(gemm_tc_kernel,
                         cudaFuncAttributeMaxDynamicSharedMemorySize, GEMM_SMEM);
    cudaFuncSetAttribute(attn_mma_kernel,
                         cudaFuncAttributeMaxDynamicSharedMemorySize, ATT_SMEM);

    const int n4a = MROWS * DD / 4;
    const int n4w = DD * DD / 4;
    dim3 gGrid(DD / 128, MROWS / 128);   // (8, 64)

    // Q projection (scores scale 1/8 folded into Q)
    split_kernel<<<n4a / 256, 256>>>(query, ah, al, n4a);
    split_kernel<<<n4w / 256, 256>>>(Wq, wh, wl, n4w);
    gemm_tc_kernel<<<gGrid, 256, GEMM_SMEM>>>(ah, al, wh, wl, bq, nullptr, qh, ql, 0.125f);
    // K projection
    split_kernel<<<n4a / 256, 256>>>(key, ah, al, n4a);
    split_kernel<<<n4w / 256, 256>>>(Wk, wh, wl, n4w);
    gemm_tc_kernel<<<gGrid, 256, GEMM_SMEM>>>(ah, al, wh, wl, bk, nullptr, kh, kl, 1.0f);
    // V projection
    split_kernel<<<n4a / 256, 256>>>(value, ah, al, n4a);
    split_kernel<<<n4w / 256, 256>>>(Wv, wh, wl, n4w);
    gemm_tc_kernel<<<gGrid, 256, GEMM_SMEM>>>(ah, al, wh, wl, bv, nullptr, vh, vl, 1.0f);

    // Attention -> (ah, al) bf16 hi/lo
    dim3 aGrid(SS / 128, BB * HH);       // (16, 64)
    attn_mma_kernel<<<aGrid, 256, ATT_SMEM>>>(qh, ql, kh, kl, vh, vl, ah, al);

    // Output projection -> fp32 d_out
    split_kernel<<<n4w / 256, 256>>>(Wo, wh, wl, n4w);
    gemm_tc_kernel<<<gGrid, 256, GEMM_SMEM>>>(ah, al, wh, wl, bo, out, nullptr, nullptr, 1.0f);
}

// round 11
// speedup vs baseline: 3.9905x; 1.0001x over previous
#include <cuda_runtime.h>
#include <cuda_bf16.h>
#include <cstdint>

// Problem constants
#define BB 4
#define SS 2048
#define DD 1024
#define HH 16
#define DKK 64
#define MROWS (BB*SS)          // 8192

// ---------------------------------------------------------------------------
// Scratch (device globals — no allocations allowed)
// ---------------------------------------------------------------------------
__device__ __nv_bfloat16 g_qh[MROWS*DD], g_ql[MROWS*DD];   // Q proj out (pre-scaled 1/8)
__device__ __nv_bfloat16 g_kh[MROWS*DD], g_kl[MROWS*DD];   // K proj out
__device__ __nv_bfloat16 g_vh[MROWS*DD], g_vl[MROWS*DD];   // V proj out
__device__ __nv_bfloat16 g_ah[MROWS*DD], g_al[MROWS*DD];   // GEMM-A splits / attn out
__device__ __nv_bfloat16 g_wh[DD*DD],   g_wl[DD*DD];       // weight splits

// ---------------------------------------------------------------------------
// Helpers
// ---------------------------------------------------------------------------
__device__ __forceinline__ uint32_t smem_u32(const void* p) {
    uint32_t a;
    asm("{ .reg .u64 t; cvta.to.shared.u64 t, %1; cvt.u32.u64 %0, t; }" : "=r"(a) : "l"(p));
    return a;
}
#define SWZ128(o) ((o) ^ (((o) >> 3) & 0x70))

#define CP_ASYNC16(dst, src) \
    asm volatile("cp.async.cg.shared.global [%0], [%1], 16;" :: "r"(dst), "l"(src))
#define CP_COMMIT()  asm volatile("cp.async.commit_group;" ::: "memory")
#define CP_WAIT0()   asm volatile("cp.async.wait_group 0;" ::: "memory")

__device__ __forceinline__ void ldsm_x4(uint32_t* r, uint32_t addr) {
    asm volatile("ldmatrix.sync.aligned.m8n8.x4.shared.b16 {%0,%1,%2,%3}, [%4];"
        : "=r"(r[0]), "=r"(r[1]), "=r"(r[2]), "=r"(r[3]) : "r"(addr));
}
__device__ __forceinline__ void ldsm_x2(uint32_t* r, uint32_t addr) {
    asm volatile("ldmatrix.sync.aligned.m8n8.x2.shared.b16 {%0,%1}, [%2];"
        : "=r"(r[0]), "=r"(r[1]) : "r"(addr));
}
__device__ __forceinline__ void ldsm_x2t(uint32_t* r, uint32_t addr) {
    asm volatile("ldmatrix.sync.aligned.m8n8.x2.trans.shared.b16 {%0,%1}, [%2];"
        : "=r"(r[0]), "=r"(r[1]) : "r"(addr));
}
__device__ __forceinline__ void mma16816(float* d, const uint32_t* a, const uint32_t* b) {
    asm volatile("mma.sync.aligned.m16n8k16.row.col.f32.bf16.bf16.f32 "
        "{%0,%1,%2,%3}, {%4,%5,%6,%7}, {%8,%9}, {%0,%1,%2,%3};"
        : "+f"(d[0]), "+f"(d[1]), "+f"(d[2]), "+f"(d[3])
        : "r"(a[0]), "r"(a[1]), "r"(a[2]), "r"(a[3]), "r"(b[0]), "r"(b[1]));
}
__device__ __forceinline__ uint32_t packbf2(float x, float y) {
    __nv_bfloat162 t = __floats2bfloat162_rn(x, y);
    return *reinterpret_cast<uint32_t*>(&t);
}

// ---------------------------------------------------------------------------
// Split fp32 -> (bf16 hi, bf16 lo) with residual capture
// ---------------------------------------------------------------------------
__global__ __launch_bounds__(256) void split_kernel(
    const float* __restrict__ x, __nv_bfloat16* __restrict__ hi,
    __nv_bfloat16* __restrict__ lo, int n4)
{
    int i = blockIdx.x * 256 + threadIdx.x;
    if (i >= n4) return;
    float4 v = reinterpret_cast<const float4*>(x)[i];
    __nv_bfloat162 h0 = __floats2bfloat162_rn(v.x, v.y);
    __nv_bfloat162 h1 = __floats2bfloat162_rn(v.z, v.w);
    float r0 = v.x - __low2float(h0), r1 = v.y - __high2float(h0);
    float r2 = v.z - __low2float(h1), r3 = v.w - __high2float(h1);
    __nv_bfloat162* hp = reinterpret_cast<__nv_bfloat162*>(hi);
    __nv_bfloat162* lp = reinterpret_cast<__nv_bfloat162*>(lo);
    hp[2*i]   = h0;
    hp[2*i+1] = h1;
    lp[2*i]   = __floats2bfloat162_rn(r0, r1);
    lp[2*i+1] = __floats2bfloat162_rn(r2, r3);
}

// ---------------------------------------------------------------------------
// HMMA bf16x3 GEMM (NT): acc = sum_k A[i,k]*W[j,k]; out = (acc + bias[j])*scale
// Output either fp32 C, or bf16 hi/lo pair (Ch,Cl).
// CTA tile 128x128, K chunk 64, SW128 smem, cp.async double-buffered.
// 8 warps in 2(m) x 4(n); warp tile 64x32 via m16n8k16.
// ---------------------------------------------------------------------------
#define TILE_BYTES 16384               // 128 rows x 128B
#define BUF_BYTES  (4*TILE_BYTES)      // Ah,Al,Bh,Bl
#define GEMM_SMEM  (1024 + 2*BUF_BYTES)

__global__ __launch_bounds__(256, 1) void gemm_tc_kernel(
    const __nv_bfloat16* __restrict__ Ah, const __nv_bfloat16* __restrict__ Al,
    const __nv_bfloat16* __restrict__ Bh, const __nv_bfloat16* __restrict__ Bl,
    const float* __restrict__ bias, float* __restrict__ C,
    __nv_bfloat16* __restrict__ Ch, __nv_bfloat16* __restrict__ Cl, float scale)
{
    extern __shared__ char smem[];
    const uint32_t sbase = (smem_u32(smem) + 1023u) & ~1023u;
    const int tid = threadIdx.x;
    const int wid = tid >> 5;
    const int lid = tid & 31;
    const int wm  = wid >> 2;          // 0..1
    const int wn  = wid & 3;           // 0..3
    const int nBase = blockIdx.x * 128;
    const int mBase = blockIdx.y * 128;

    const uint4* srcs[4] = {
        reinterpret_cast<const uint4*>(Ah) + (size_t)mBase * 128,
        reinterpret_cast<const uint4*>(Al) + (size_t)mBase * 128,
        reinterpret_cast<const uint4*>(Bh) + (size_t)nBase * 128,
        reinterpret_cast<const uint4*>(Bl) + (size_t)nBase * 128
    };

    auto load_chunk = [&](int ch, int buf) {
        const int kq = ch * 8;
        const uint32_t bufAddr = sbase + buf * BUF_BYTES;
#pragma unroll
        for (int t = 0; t < 16; t++) {
            const int tile = t >> 2;
            const int i = tid + (t & 3) * 256;
            const int r = i >> 3, c = i & 7;
            const uint4* src = srcs[tile] + (size_t)r * 128 + kq + c;
            uint32_t dst = bufAddr + tile * TILE_BYTES + SWZ128(r * 128 + c * 16);
            CP_ASYNC16(dst, src);
        }
        CP_COMMIT();
    };

    float acc[4][4][4];
#pragma unroll
    for (int mt = 0; mt < 4; mt++)
#pragma unroll
        for (int nt = 0; nt < 4; nt++)
#pragma unroll
            for (int r = 0; r < 4; r++) acc[mt][nt][r] = 0.f;

    load_chunk(0, 0);
    CP_WAIT0();
    __syncthreads();

    const int aRow = wm * 64 + (lid & 15);
    const int aColH = (lid >> 4) * 16;
    const int bRow = wn * 32 + (lid & 7);
    const int bColH = ((lid >> 3) & 1) * 16;

#pragma unroll 1
    for (int ch = 0; ch < 16; ch++) {
        const int cur = ch & 1;
        if (ch < 15) load_chunk(ch + 1, cur ^ 1);

        const uint32_t bufAddr = sbase + cur * BUF_BYTES;
        const uint32_t aH = bufAddr;
        const uint32_t aL = bufAddr + TILE_BYTES;
        const uint32_t bH = bufAddr + 2 * TILE_BYTES;
        const uint32_t bL = bufAddr + 3 * TILE_BYTES;

#pragma unroll
        for (int ks = 0; ks < 4; ks++) {
            const int kByte = ks * 32;
            uint32_t ah[4][4], al[4][4], bh[4][2], bl[4][2];
#pragma unroll
            for (int mt = 0; mt < 4; mt++) {
                uint32_t off = SWZ128((aRow + mt * 16) * 128 + kByte + aColH);
                ldsm_x4(ah[mt], aH + off);
                ldsm_x4(al[mt], aL + off);
            }
#pragma unroll
            for (int nt = 0; nt < 4; nt++) {
                uint32_t off = SWZ128((bRow + nt * 8) * 128 + kByte + bColH);
                ldsm_x2(bh[nt], bH + off);
                ldsm_x2(bl[nt], bL + off);
            }
#pragma unroll
            for (int mt = 0; mt < 4; mt++)
#pragma unroll
                for (int nt = 0; nt < 4; nt++) {
                    mma16816(acc[mt][nt], ah[mt], bh[nt]);
                    mma16816(acc[mt][nt], ah[mt], bl[nt]);
                    mma16816(acc[mt][nt], al[mt], bh[nt]);
                }
        }

        if (ch < 15) CP_WAIT0();
        __syncthreads();
    }

    // Epilogue
    const int erow = mBase + wm * 64 + (lid >> 2);
    const int ecolBase = nBase + wn * 32 + 2 * (lid & 3);
#pragma unroll
    for (int nt = 0; nt < 4; nt++) {
        const int col = ecolBase + nt * 8;
        const float b0 = __ldg(bias + col), b1 = __ldg(bias + col + 1);
#pragma unroll
        for (int mt = 0; mt < 4; mt++) {
            const int r0 = erow + mt * 16;
            float v0 = (acc[mt][nt][0] + b0) * scale;
            float v1 = (acc[mt][nt][1] + b1) * scale;
            float v2 = (acc[mt][nt][2] + b0) * scale;
            float v3 = (acc[mt][nt][3] + b1) * scale;
            if (C) {
                *reinterpret_cast<float2*>(C + (size_t)r0 * DD + col)       = make_float2(v0, v1);
                *reinterpret_cast<float2*>(C + (size_t)(r0 + 8) * DD + col) = make_float2(v2, v3);
            } else {
                __nv_bfloat162 h0 = __floats2bfloat162_rn(v0, v1);
                __nv_bfloat162 h1 = __floats2bfloat162_rn(v2, v3);
                *reinterpret_cast<__nv_bfloat162*>(Ch + (size_t)r0 * DD + col)       = h0;
                *reinterpret_cast<__nv_bfloat162*>(Ch + (size_t)(r0 + 8) * DD + col) = h1;
                *reinterpret_cast<__nv_bfloat162*>(Cl + (size_t)r0 * DD + col) =
                    __floats2bfloat162_rn(v0 - __low2float(h0), v1 - __high2float(h0));
                *reinterpret_cast<__nv_bfloat162*>(Cl + (size_t)(r0 + 8) * DD + col) =
                    __floats2bfloat162_rn(v2 - __low2float(h1), v3 - __high2float(h1));
            }
        }
    }
}

// ---------------------------------------------------------------------------
// MMA flash attention. Q pre-scaled by 1/8. All operands bf16 hi/lo in
// [B,S,D] layout (head h = cols h*64..+63). Output -> (Oh,Ol) bf16 hi/lo.
// CTA: 128 query rows x one (b,h); 8 warps x 16 rows; BK=32 keys/iter.
// scores = Qh*Kh + Qh*Kl + Ql*Kh ; PV = Ph*Vh + Ph*Vl + Pl*Vh (fp32 acc).
// P A-fragments come directly from score accumulators (layout identity).
// ---------------------------------------------------------------------------
#define KV_BYTES 16384                 // Kh,Kl,Vh,Vl 32x128B each
#define ATT_SMEM (32768 + 2*KV_BYTES + 1024)

__global__ __launch_bounds__(256, 2) void attn_mma_kernel(
    const __nv_bfloat16* __restrict__ Qh, const __nv_bfloat16* __restrict__ Ql,
    const __nv_bfloat16* __restrict__ Kh, const __nv_bfloat16* __restrict__ Kl,
    const __nv_bfloat16* __restrict__ Vh, const __nv_bfloat16* __restrict__ Vl,
    __nv_bfloat16* __restrict__ Oh, __nv_bfloat16* __restrict__ Ol)
{
    extern __shared__ char smem[];
    const uint32_t sb = (smem_u32(smem) + 1023u) & ~1023u;
    const int tid = threadIdx.x;
    const int wid = tid >> 5;
    const int lid = tid & 31;
    const int bh  = blockIdx.y;
    const int b   = bh >> 4, h = bh & 15;
    const int qBase = blockIdx.x * 128;

    const uint32_t QH_OFF = 0, QL_OFF = 16384, KV_OFF = 32768;
    const size_t qOrg = (size_t)(b * SS + qBase) * DD + h * DKK;   // Q tile origin (elems)
    const size_t kOrg = (size_t)(b * SS) * DD + h * DKK;           // K/V batch origin

    // ---- stage Q (hi/lo) : 2 x 128 rows x 8 chunks of 16B ----
    {
        const int idx = tid & 1023;        // placeholder to keep pattern clear
        (void)idx;
#pragma unroll
        for (int j = 0; j < 8; j++) {
            int i  = tid + j * 256;        // 0..2047
            int sp = i >> 10;              // 0=hi 1=lo
            int r  = (i & 1023) >> 3;
            int c  = i & 7;
            const __nv_bfloat16* src = (sp ? Ql : Qh) + qOrg + (size_t)r * DD + c * 8;
            uint32_t dst = sb + (sp ? QL_OFF : QH_OFF) + SWZ128(r * 128 + c * 16);
            CP_ASYNC16(dst, src);
        }
    }
    // ---- K/V tile loader: 32 keys x 64 dims, 4 tiles (Kh,Kl,Vh,Vl) ----
    const __nv_bfloat16* kvsrc[4] = { Kh, Kl, Vh, Vl };
    auto load_kv = [&](int t, int buf) {
        const int r = tid >> 3, c = tid & 7;             // r 0..31, c 0..7
        const size_t g = kOrg + (size_t)(t * 32 + r) * DD + c * 8;
        const uint32_t dstb = sb + KV_OFF + buf * KV_BYTES + SWZ128(r * 128 + c * 16);
#pragma unroll
        for (int tile = 0; tile < 4; tile++)
            CP_ASYNC16(dstb + tile * 4096, kvsrc[tile] + g);
        CP_COMMIT();
    };

    load_kv(0, 0);
    CP_WAIT0();
    __syncthreads();

    // ---- Q fragments (held in regs for whole kernel) ----
    uint32_t qfh[4][4], qfl[4][4];
    {
        const int aRow = wid * 16 + (lid & 15);
        const int aColH = (lid >> 4) * 16;
#pragma unroll
        for (int ks = 0; ks < 4; ks++) {
            uint32_t off = SWZ128(aRow * 128 + ks * 32 + aColH);
            ldsm_x4(qfh[ks], sb + QH_OFF + off);
            ldsm_x4(qfl[ks], sb + QL_OFF + off);
        }
    }

    float o[8][4];
#pragma unroll
    for (int nt = 0; nt < 8; nt++)
#pragma unroll
        for (int r = 0; r < 4; r++) o[nt][r] = 0.f;
    float m0 = -1e30f, m1 = -1e30f, l0 = 0.f, l1 = 0.f;

    // fragment address components
    const uint32_t kFragBase = (lid & 7) * 128 + ((lid >> 3) & 1) * 16;       // + nt*1024 + ks*32
    const uint32_t vFragRow  = ((lid & 7) + 8 * ((lid >> 3) & 1)) * 128;      // + ks*2048 + nt*16

#pragma unroll 1
    for (int t = 0; t < SS / 32; t++) {
        const int cur = t & 1;
        if (t < SS / 32 - 1) load_kv(t + 1, cur ^ 1);

        const uint32_t kb = sb + KV_OFF + cur * KV_BYTES;

        // ---- scores: m16 x n32 x k64, bf16x3 ----
        float s[4][4];
#pragma unroll
        for (int nt = 0; nt < 4; nt++)
#pragma unroll
            for (int r = 0; r < 4; r++) s[nt][r] = 0.f;
#pragma unroll
        for (int ks = 0; ks < 4; ks++) {
#pragma unroll
            for (int nt = 0; nt < 4; nt++) {
                uint32_t kbh[2], kbl[2];
                uint32_t off = SWZ128(nt * 1024 + kFragBase + ks * 32);
                ldsm_x2(kbh, kb + off);            // Kh tile @ +0
                ldsm_x2(kbl, kb + 4096 + off);     // Kl tile
                mma16816(s[nt], qfh[ks], kbh);
                mma16816(s[nt], qfh[ks], kbl);
                mma16816(s[nt], qfl[ks], kbh);
            }
        }

        // ---- online softmax (rows r=lid>>2 and r+8; cols across lanes lid&3) ----
        float t0 = -1e30f, t1 = -1e30f;
#pragma unroll
        for (int nt = 0; nt < 4; nt++) {
            t0 = fmaxf(t0, fmaxf(s[nt][0], s[nt][1]));
            t1 = fmaxf(t1, fmaxf(s[nt][2], s[nt][3]));
        }
        t0 = fmaxf(t0, __shfl_xor_sync(0xffffffffu, t0, 1));
        t0 = fmaxf(t0, __shfl_xor_sync(0xffffffffu, t0, 2));
        t1 = fmaxf(t1, __shfl_xor_sync(0xffffffffu, t1, 1));
        t1 = fmaxf(t1, __shfl_xor_sync(0xffffffffu, t1, 2));
        const float mn0 = fmaxf(m0, t0), mn1 = fmaxf(m1, t1);
        const float c0 = __expf(m0 - mn0), c1 = __expf(m1 - mn1);
        m0 = mn0; m1 = mn1;

        uint32_t aPh[2][4], aPl[2][4];
        float rs0 = 0.f, rs1 = 0.f;
#pragma unroll
        for (int nt = 0; nt < 4; nt++) {
            float p0 = __expf(s[nt][0] - m0);
            float p1 = __expf(s[nt][1] - m0);
            float p2 = __expf(s[nt][2] - m1);
            float p3 = __expf(s[nt][3] - m1);
            rs0 += p0 + p1; rs1 += p2 + p3;
            const int ks = nt >> 1, pos = (nt & 1) * 2;
            __nv_bfloat162 hA = __floats2bfloat162_rn(p0, p1);
            __nv_bfloat162 hB = __floats2bfloat162_rn(p2, p3);
            aPh[ks][pos]     = *reinterpret_cast<uint32_t*>(&hA);
            aPh[ks][pos + 1] = *reinterpret_cast<uint32_t*>(&hB);
            aPl[ks][pos]     = packbf2(p0 - __low2float(hA), p1 - __high2float(hA));
            aPl[ks][pos + 1] = packbf2(p2 - __low2float(hB), p3 - __high2float(hB));
        }
        rs0 += __shfl_xor_sync(0xffffffffu, rs0, 1);
        rs0 += __shfl_xor_sync(0xffffffffu, rs0, 2);
        rs1 += __shfl_xor_sync(0xffffffffu, rs1, 1);
        rs1 += __shfl_xor_sync(0xffffffffu, rs1, 2);
        l0 = l0 * c0 + rs0;
        l1 = l1 * c1 + rs1;

#pragma unroll
        for (int nt = 0; nt < 8; nt++) {
            o[nt][0] *= c0; o[nt][1] *= c0;
            o[nt][2] *= c1; o[nt][3] *= c1;
        }

        // ---- PV: m16 x n64 x k32, bf16x3 (V via ldmatrix.trans) ----
#pragma unroll
        for (int ks = 0; ks < 2; ks++) {
#pragma unroll
            for (int nt = 0; nt < 8; nt++) {
                uint32_t vbh[2], vbl[2];
                uint32_t off = SWZ128(ks * 2048 + vFragRow + nt * 16);
                ldsm_x2t(vbh, kb + 8192 + off);     // Vh tile
                ldsm_x2t(vbl, kb + 12288 + off);    // Vl tile
                mma16816(o[nt], aPh[ks], vbh);
                mma16816(o[nt], aPh[ks], vbl);
                mma16816(o[nt], aPl[ks], vbh);
            }
        }

        CP_WAIT0();
        __syncthreads();
    }

    // ---- epilogue: normalize, split to bf16 hi/lo, write [B,S,D] ----
    const float i0 = 1.f / l0, i1 = 1.f / l1;
    const size_t row0 = (size_t)(b * SS + qBase + wid * 16 + (lid >> 2));
    const int colBase = h * DKK + 2 * (lid & 3);
#pragma unroll
    for (int nt = 0; nt < 8; nt++) {
        const int col = colBase + nt * 8;
        float v0 = o[nt][0] * i0, v1 = o[nt][1] * i0;
        float v2 = o[nt][2] * i1, v3 = o[nt][3] * i1;
        __nv_bfloat162 h0 = __floats2bfloat162_rn(v0, v1);
        __nv_bfloat162 h1 = __floats2bfloat162_rn(v2, v3);
        *reinterpret_cast<__nv_bfloat162*>(Oh + row0 * DD + col)       = h0;
        *reinterpret_cast<__nv_bfloat162*>(Oh + (row0 + 8) * DD + col) = h1;
        *reinterpret_cast<__nv_bfloat162*>(Ol + row0 * DD + col) =
            __floats2bfloat162_rn(v0 - __low2float(h0), v1 - __high2float(h0));
        *reinterpret_cast<__nv_bfloat162*>(Ol + (row0 + 8) * DD + col) =
            __floats2bfloat162_rn(v2 - __low2float(h1), v3 - __high2float(h1));
    }
}

// ---------------------------------------------------------------------------
// kernel_launch
// ---------------------------------------------------------------------------
extern "C" void kernel_launch(void* const* d_in, const int* in_sizes, int n_in,
                              void* d_out, int out_size)
{
    const float* query = (const float*)d_in[0];
    const float* key   = (const float*)d_in[1];
    const float* value = (const float*)d_in[2];
    const float* Wq    = (const float*)d_in[3];
    const float* bq    = (const float*)d_in[4];
    const float* Wk    = (const float*)d_in[5];
    const float* bk    = (const float*)d_in[6];
    const float* Wv    = (const float*)d_in[7];
    const float* bv    = (const float*)d_in[8];
    const float* Wo    = (const float*)d_in[9];
    const float* bo    = (const float*)d_in[10];
    float* out = (float*)d_out;

    __nv_bfloat16 *qh, *ql, *kh, *kl, *vh, *vl, *ah, *al, *wh, *wl;
    cudaGetSymbolAddress((void**)&qh, g_qh);
    cudaGetSymbolAddress((void**)&ql, g_ql);
    cudaGetSymbolAddress((void**)&kh, g_kh);
    cudaGetSymbolAddress((void**)&kl, g_kl);
    cudaGetSymbolAddress((void**)&vh, g_vh);
    cudaGetSymbolAddress((void**)&vl, g_vl);
    cudaGetSymbolAddress((void**)&ah, g_ah);
    cudaGetSymbolAddress((void**)&al, g_al);
    cudaGetSymbolAddress((void**)&wh, g_wh);
    cudaGetSymbolAddress((void**)&wl, g_wl);

    cudaFuncSetAttribute(gemm_tc_kernel,
                         cudaFuncAttributeMaxDynamicSharedMemorySize, GEMM_SMEM);
    cudaFuncSetAttribute(attn_mma_kernel,
                         cudaFuncAttributeMaxDynamicSharedMemorySize, ATT_SMEM);

    const int n4a = MROWS * DD / 4;
    const int n4w = DD * DD / 4;
    dim3 gGrid(DD / 128, MROWS / 128);   // (8, 64)

    // Q projection (scores scale 1/8 folded into Q)
    split_kernel<<<n4a / 256, 256>>>(query, ah, al, n4a);
    split_kernel<<<n4w / 256, 256>>>(Wq, wh, wl, n4w);
    gemm_tc_kernel<<<gGrid, 256, GEMM_SMEM>>>(ah, al, wh, wl, bq, nullptr, qh, ql, 0.125f);
    // K projection
    split_kernel<<<n4a / 256, 256>>>(key, ah, al, n4a);
    split_kernel<<<n4w / 256, 256>>>(Wk, wh, wl, n4w);
    gemm_tc_kernel<<<gGrid, 256, GEMM_SMEM>>>(ah, al, wh, wl, bk, nullptr, kh, kl, 1.0f);
    // V projection
    split_kernel<<<n4a / 256, 256>>>(value, ah, al, n4a);
    split_kernel<<<n4w / 256, 256>>>(Wv, wh, wl, n4w);
    gemm_tc_kernel<<<gGrid, 256, GEMM_SMEM>>>(ah, al, wh, wl, bv, nullptr, vh, vl, 1.0f);

    // Attention -> (ah, al) bf16 hi/lo
    dim3 aGrid(SS / 128, BB * HH);       // (16, 64)
    attn_mma_kernel<<<aGrid, 256, ATT_SMEM>>>(qh, ql, kh, kl, vh, vl, ah, al);

    // Output projection -> fp32 d_out
    split_kernel<<<n4w / 256, 256>>>(Wo, wh, wl, n4w);
    gemm_tc_kernel<<<gGrid, 256, GEMM_SMEM>>>(ah, al, wh, wl, bo, out, nullptr, nullptr, 1.0f);
}